// round 1
// baseline (speedup 1.0000x reference)
#include <cuda_runtime.h>

#define NN 50000
#define NE 800000
#define NG 128
#define FE 16
#define DD 64

// ---------------- scratch (static device globals; no allocation) ----------------
__device__ int   d_counts[NN];
__device__ int   d_offsets[NN + 1];
__device__ int   d_cursor[NN];
__device__ int   d_src_sorted[NE];
__device__ int   d_eid_sorted[NE];
__device__ float d_agg16[NN * FE];
__device__ float d_msg[NN * DD];
__device__ float d_hA[NN * DD];
__device__ float d_hB[NN * DD];
__device__ float d_g[NN * DD];

// ---------------- K0: zero output + histogram counters ----------------
__global__ void zero_kernel(float* __restrict__ out) {
    int i = blockIdx.x * blockDim.x + threadIdx.x;
    if (i < NG * DD) out[i] = 0.f;
    if (i < NN) d_counts[i] = 0;
}

// ---------------- K1: histogram of edge_dst ----------------
__global__ void hist_kernel(const int* __restrict__ dst) {
    int e = blockIdx.x * blockDim.x + threadIdx.x;
    if (e < NE) atomicAdd(&d_counts[dst[e]], 1);
}

// ---------------- K2: single-block exclusive scan -> offsets & cursors ----------------
__global__ void scan_kernel() {
    __shared__ int sm[1024];
    const int T = 1024;
    const int C = (NN + T - 1) / T;  // 49
    int t = threadIdx.x;
    int base = t * C;
    int local = 0;
    for (int j = 0; j < C; j++) {
        int i = base + j;
        if (i < NN) local += d_counts[i];
    }
    sm[t] = local;
    __syncthreads();
    for (int d = 1; d < T; d <<= 1) {
        int v = (t >= d) ? sm[t - d] : 0;
        __syncthreads();
        sm[t] += v;
        __syncthreads();
    }
    int run = (t == 0) ? 0 : sm[t - 1];
    for (int j = 0; j < C; j++) {
        int i = base + j;
        if (i < NN) {
            d_offsets[i] = run;
            d_cursor[i] = run;
            run += d_counts[i];
        }
    }
    if (t == T - 1) d_offsets[NN] = sm[T - 1];
}

// ---------------- K3: scatter edges into CSR order ----------------
__global__ void scatter_kernel(const int* __restrict__ src, const int* __restrict__ dst) {
    int e = blockIdx.x * blockDim.x + threadIdx.x;
    if (e < NE) {
        int dn = dst[e];
        int p = atomicAdd(&d_cursor[dn], 1);
        d_src_sorted[p] = src[e];
        d_eid_sorted[p] = e;
    }
}

// ---------------- K4a: per-node sum of incident edge features (16-dim) ----------------
__global__ __launch_bounds__(256) void agg_edge_kernel(const float* __restrict__ ef) {
    int node = blockIdx.x * 8 + (threadIdx.x >> 5);
    if (node >= NN) return;
    int lane = threadIdx.x & 31;
    int s = d_offsets[node], e = d_offsets[node + 1];
    int f = lane & 15, half = lane >> 4;
    float acc = 0.f;
    for (int p = s + half; p < e; p += 2) {
        int eid = d_eid_sorted[p];
        acc += ef[eid * FE + f];
    }
    acc += __shfl_xor_sync(0xffffffffu, acc, 16);
    if (lane < 16) d_agg16[node * FE + lane] = acc;
}

// ---------------- K4b: input_message = nf@Wn + bn + agg16@We + deg*be ; h0 = relu ----------------
__global__ __launch_bounds__(256) void init_kernel(
    const float* __restrict__ nf, const float* __restrict__ Wn, const float* __restrict__ bn,
    const float* __restrict__ We, const float* __restrict__ be) {
    __shared__ float sWn[64 * 64];
    __shared__ float sWe[16 * 64];
    __shared__ float sbn[64], sbe[64];
    int t = threadIdx.x;
    for (int i = t; i < 64 * 64; i += 256) sWn[i] = Wn[i];
    for (int i = t; i < 16 * 64; i += 256) sWe[i] = We[i];
    if (t < 64) { sbn[t] = bn[t]; sbe[t] = be[t]; }
    __syncthreads();
    int warp = t >> 5, lane = t & 31;
    int rowbase = (blockIdx.x * 8 + warp) * 8;
    if (rowbase >= NN) return;
    float xa[8], xb[8], xe[8], a0[8], a1[8];
#pragma unroll
    for (int r = 0; r < 8; r++) {
        int row = rowbase + r;
        bool v = row < NN;
        xa[r] = v ? nf[row * 64 + lane] : 0.f;
        xb[r] = v ? nf[row * 64 + lane + 32] : 0.f;
        xe[r] = (v && lane < 16) ? d_agg16[row * 16 + lane] : 0.f;
        a0[r] = 0.f;
        a1[r] = 0.f;
    }
#pragma unroll 4
    for (int k = 0; k < 64; k++) {
        float w0 = sWn[k * 64 + lane], w1 = sWn[k * 64 + lane + 32];
#pragma unroll
        for (int r = 0; r < 8; r++) {
            float xk = __shfl_sync(0xffffffffu, (k < 32) ? xa[r] : xb[r], k & 31);
            a0[r] += xk * w0;
            a1[r] += xk * w1;
        }
    }
#pragma unroll 4
    for (int k = 0; k < 16; k++) {
        float w0 = sWe[k * 64 + lane], w1 = sWe[k * 64 + lane + 32];
#pragma unroll
        for (int r = 0; r < 8; r++) {
            float xk = __shfl_sync(0xffffffffu, xe[r], k);
            a0[r] += xk * w0;
            a1[r] += xk * w1;
        }
    }
#pragma unroll
    for (int r = 0; r < 8; r++) {
        int row = rowbase + r;
        if (row >= NN) break;
        float deg = (float)(d_offsets[row + 1] - d_offsets[row]);
        float m0 = a0[r] + sbn[lane] + deg * sbe[lane];
        float m1 = a1[r] + sbn[lane + 32] + deg * sbe[lane + 32];
        d_msg[row * 64 + lane] = m0;
        d_msg[row * 64 + lane + 32] = m1;
        d_hA[row * 64 + lane] = fmaxf(m0, 0.f);
        d_hA[row * 64 + lane + 32] = fmaxf(m1, 0.f);
    }
}

// ---------------- K5: dense g = h @ W  (64x64, row-blocked, FMA-bound) ----------------
__global__ __launch_bounds__(256) void gemm64_kernel(const float* __restrict__ W, int in_sel) {
    __shared__ float sW[64 * 64];
    const float* __restrict__ X = in_sel ? d_hB : d_hA;
    int t = threadIdx.x;
    for (int i = t; i < 4096; i += 256) sW[i] = W[i];
    __syncthreads();
    int warp = t >> 5, lane = t & 31;
    int rowbase = (blockIdx.x * 8 + warp) * 8;
    if (rowbase >= NN) return;
    float xa[8], xb[8], a0[8], a1[8];
#pragma unroll
    for (int r = 0; r < 8; r++) {
        int row = rowbase + r;
        bool v = row < NN;
        xa[r] = v ? X[row * 64 + lane] : 0.f;
        xb[r] = v ? X[row * 64 + lane + 32] : 0.f;
        a0[r] = 0.f;
        a1[r] = 0.f;
    }
#pragma unroll 4
    for (int k = 0; k < 64; k++) {
        float w0 = sW[k * 64 + lane], w1 = sW[k * 64 + lane + 32];
#pragma unroll
        for (int r = 0; r < 8; r++) {
            float xk = __shfl_sync(0xffffffffu, (k < 32) ? xa[r] : xb[r], k & 31);
            a0[r] += xk * w0;
            a1[r] += xk * w1;
        }
    }
#pragma unroll
    for (int r = 0; r < 8; r++) {
        int row = rowbase + r;
        if (row >= NN) break;
        d_g[row * 64 + lane] = a0[r];
        d_g[row * 64 + lane + 32] = a1[r];
    }
}

// ---------------- K6: h_out = relu( segsum_dst(g[src]) + b + msg )  (warp/node CSR gather) ----------------
__global__ __launch_bounds__(512) void gather_kernel(const float* __restrict__ bc, int out_sel) {
    int node = blockIdx.x * 16 + (threadIdx.x >> 5);
    if (node >= NN) return;
    int lane = threadIdx.x & 31;
    float* __restrict__ hout = out_sel ? d_hB : d_hA;
    const float* __restrict__ g = d_g;
    int s = d_offsets[node], e = d_offsets[node + 1];
    float2 acc0 = make_float2(0.f, 0.f), acc1 = make_float2(0.f, 0.f);
    int p = s;
    for (; p + 2 <= e; p += 2) {
        int s0 = d_src_sorted[p];
        int s1 = d_src_sorted[p + 1];
        float2 v0 = *(const float2*)(g + s0 * 64 + 2 * lane);
        float2 v1 = *(const float2*)(g + s1 * 64 + 2 * lane);
        acc0.x += v0.x; acc0.y += v0.y;
        acc1.x += v1.x; acc1.y += v1.y;
    }
    if (p < e) {
        int s0 = d_src_sorted[p];
        float2 v0 = *(const float2*)(g + s0 * 64 + 2 * lane);
        acc0.x += v0.x; acc0.y += v0.y;
    }
    float2 b2 = *(const float2*)(bc + 2 * lane);
    float2 m2 = *(const float2*)(d_msg + node * 64 + 2 * lane);
    float2 o;
    o.x = fmaxf(acc0.x + acc1.x + b2.x + m2.x, 0.f);
    o.y = fmaxf(acc0.y + acc1.y + b2.y + m2.y, 0.f);
    *(float2*)(hout + node * 64 + 2 * lane) = o;
}

// ---------------- K7: out = relu(h@Wf + bf) -> graph sum-pool (register pre-reduction) ----------------
__global__ __launch_bounds__(256) void final_kernel(
    const float* __restrict__ Wf, const float* __restrict__ bf,
    const int* __restrict__ gid, float* __restrict__ out, int in_sel) {
    __shared__ float sW[64 * 64];
    __shared__ float sb[64];
    const float* __restrict__ X = in_sel ? d_hB : d_hA;
    int t = threadIdx.x;
    for (int i = t; i < 4096; i += 256) sW[i] = Wf[i];
    if (t < 64) sb[t] = bf[t];
    __syncthreads();
    int warp = t >> 5, lane = t & 31;
    int rowbase = (blockIdx.x * 8 + warp) * 8;
    if (rowbase >= NN) return;
    float xa[8], xb[8], a0[8], a1[8];
#pragma unroll
    for (int r = 0; r < 8; r++) {
        int row = rowbase + r;
        bool v = row < NN;
        xa[r] = v ? X[row * 64 + lane] : 0.f;
        xb[r] = v ? X[row * 64 + lane + 32] : 0.f;
        a0[r] = sb[lane];
        a1[r] = sb[lane + 32];
    }
#pragma unroll 4
    for (int k = 0; k < 64; k++) {
        float w0 = sW[k * 64 + lane], w1 = sW[k * 64 + lane + 32];
#pragma unroll
        for (int r = 0; r < 8; r++) {
            float xk = __shfl_sync(0xffffffffu, (k < 32) ? xa[r] : xb[r], k & 31);
            a0[r] += xk * w0;
            a1[r] += xk * w1;
        }
    }
#pragma unroll
    for (int r = 0; r < 8; r++) {
        a0[r] = fmaxf(a0[r], 0.f);
        a1[r] = fmaxf(a1[r], 0.f);
    }
    // graph_id is sorted: most 8-row groups map to one graph -> pre-reduce in registers
    bool full = (rowbase + 8 <= NN);
    int g0 = gid[rowbase];
    bool uni = full;
    if (full) {
#pragma unroll
        for (int r = 1; r < 8; r++) uni = uni && (gid[rowbase + r] == g0);
    }
    if (uni) {
        float s0 = 0.f, s1 = 0.f;
#pragma unroll
        for (int r = 0; r < 8; r++) { s0 += a0[r]; s1 += a1[r]; }
        atomicAdd(&out[g0 * 64 + lane], s0);
        atomicAdd(&out[g0 * 64 + lane + 32], s1);
    } else {
#pragma unroll
        for (int r = 0; r < 8; r++) {
            int row = rowbase + r;
            if (row >= NN) break;
            int gg = gid[row];
            atomicAdd(&out[gg * 64 + lane], a0[r]);
            atomicAdd(&out[gg * 64 + lane + 32], a1[r]);
        }
    }
}

// ---------------- host ----------------
extern "C" void kernel_launch(void* const* d_in, const int* in_sizes, int n_in,
                              void* d_out, int out_size) {
    const float *nf = 0, *ef = 0, *Wn = 0, *bn = 0, *We = 0, *be = 0;
    const float *Wc = 0, *bc = 0, *Wf = 0, *bf = 0;
    const int *esrc = 0, *edst = 0, *gid = 0;
    int n800 = 0, n4096 = 0, n64 = 0;
    for (int i = 0; i < n_in; i++) {
        int sz = in_sizes[i];
        const void* p = d_in[i];
        if (sz == NN * 64)      nf = (const float*)p;
        else if (sz == NE * 16) ef = (const float*)p;
        else if (sz == NE)      { if (n800++ == 0) esrc = (const int*)p; else edst = (const int*)p; }
        else if (sz == NN)      gid = (const int*)p;
        else if (sz == 4096)    { if (n4096++ == 0) Wn = (const float*)p; else Wf = (const float*)p; }
        else if (sz == 1024)    We = (const float*)p;
        else if (sz == 12288)   Wc = (const float*)p;
        else if (sz == 192)     bc = (const float*)p;
        else if (sz == 64)      { if (n64 == 0) bn = (const float*)p;
                                  else if (n64 == 1) be = (const float*)p;
                                  else bf = (const float*)p; n64++; }
    }
    float* out = (float*)d_out;

    zero_kernel<<<(NN + 255) / 256, 256>>>(out);
    hist_kernel<<<(NE + 255) / 256, 256>>>(edst);
    scan_kernel<<<1, 1024>>>();
    scatter_kernel<<<(NE + 255) / 256, 256>>>(esrc, edst);
    agg_edge_kernel<<<(NN + 7) / 8, 256>>>(ef);
    init_kernel<<<(NN + 63) / 64, 256>>>(nf, Wn, bn, We, be);

    int cur = 0;  // 0 -> current h in d_hA
    for (int lv = 0; lv < 3; lv++) {
        gemm64_kernel<<<(NN + 63) / 64, 256>>>(Wc + lv * 4096, cur);
        gather_kernel<<<(NN + 15) / 16, 512>>>(bc + lv * 64, cur ^ 1);
        cur ^= 1;
    }
    final_kernel<<<(NN + 63) / 64, 256>>>(Wf, bf, gid, out, cur);
}

// round 2
// speedup vs baseline: 1.0121x; 1.0121x over previous
#include <cuda_runtime.h>
#include <cuda_fp16.h>

#define NN 50000
#define NE 800000
#define NG 128
#define FE 16
#define DD 64

// ---------------- scratch (static device globals; no allocation) ----------------
__device__ int    d_counts[NN];
__device__ int    d_offsets[NN + 1];
__device__ int    d_cursor[NN];
__device__ int2   d_se[NE];          // (src, eid) packed, CSR order by dst
__device__ float  d_agg16[NN * FE];
__device__ __half d_msg[NN * DD];
__device__ __half d_hA[NN * DD];
__device__ __half d_hB[NN * DD];

// ---------------- K0: zero output + histogram counters ----------------
__global__ void zero_kernel(float* __restrict__ out) {
    int i = blockIdx.x * blockDim.x + threadIdx.x;
    if (i < NG * DD) out[i] = 0.f;
    if (i < NN) d_counts[i] = 0;
}

// ---------------- K1: histogram of edge_dst ----------------
__global__ void hist_kernel(const int* __restrict__ dst) {
    int e = blockIdx.x * blockDim.x + threadIdx.x;
    if (e < NE) atomicAdd(&d_counts[dst[e]], 1);
}

// ---------------- K2: single-block exclusive scan -> offsets & cursors ----------------
__global__ void scan_kernel() {
    __shared__ int sm[1024];
    const int T = 1024;
    const int C = (NN + T - 1) / T;
    int t = threadIdx.x;
    int base = t * C;
    int local = 0;
    for (int j = 0; j < C; j++) {
        int i = base + j;
        if (i < NN) local += d_counts[i];
    }
    sm[t] = local;
    __syncthreads();
    for (int d = 1; d < T; d <<= 1) {
        int v = (t >= d) ? sm[t - d] : 0;
        __syncthreads();
        sm[t] += v;
        __syncthreads();
    }
    int run = (t == 0) ? 0 : sm[t - 1];
    for (int j = 0; j < C; j++) {
        int i = base + j;
        if (i < NN) {
            d_offsets[i] = run;
            d_cursor[i] = run;
            run += d_counts[i];
        }
    }
    if (t == T - 1) d_offsets[NN] = sm[T - 1];
}

// ---------------- K3: scatter edges into CSR order (4 edges/thread, int2 stores) ----------------
__global__ void scatter_kernel(const int* __restrict__ src, const int* __restrict__ dst) {
    int base = (blockIdx.x * blockDim.x + threadIdx.x) * 4;
#pragma unroll
    for (int j = 0; j < 4; j++) {
        int e = base + j;
        if (e < NE) {
            int dn = dst[e];
            int p = atomicAdd(&d_cursor[dn], 1);
            d_se[p] = make_int2(src[e], e);
        }
    }
}

// ---------------- K4a: per-node sum of incident edge features (16-dim) ----------------
__global__ __launch_bounds__(256) void agg_edge_kernel(const float* __restrict__ ef) {
    int node = blockIdx.x * 8 + (threadIdx.x >> 5);
    if (node >= NN) return;
    int lane = threadIdx.x & 31;
    int s = d_offsets[node], e = d_offsets[node + 1];
    int f = lane & 15, half = lane >> 4;
    float acc0 = 0.f, acc1 = 0.f;
    int p = s + half;
    for (; p + 2 < e; p += 4) {
        int e0 = d_se[p].y;
        int e1 = d_se[p + 2].y;
        acc0 += ef[e0 * FE + f];
        acc1 += ef[e1 * FE + f];
    }
    if (p < e) acc0 += ef[d_se[p].y * FE + f];
    float acc = acc0 + acc1;
    acc += __shfl_xor_sync(0xffffffffu, acc, 16);
    if (lane < 16) d_agg16[node * FE + lane] = acc;
}

// ---------------- K4b: msg = nf@Wn + bn + agg16@We + deg*be ; h0 = relu(msg) (fp16 out) ----------------
__global__ __launch_bounds__(256) void init_kernel(
    const float* __restrict__ nf, const float* __restrict__ Wn, const float* __restrict__ bn,
    const float* __restrict__ We, const float* __restrict__ be) {
    __shared__ float sWn[64 * 64];
    __shared__ float sWe[16 * 64];
    __shared__ float sbn[64], sbe[64];
    int t = threadIdx.x;
    for (int i = t; i < 64 * 64; i += 256) sWn[i] = Wn[i];
    for (int i = t; i < 16 * 64; i += 256) sWe[i] = We[i];
    if (t < 64) { sbn[t] = bn[t]; sbe[t] = be[t]; }
    __syncthreads();
    int warp = t >> 5, lane = t & 31;
    int rowbase = (blockIdx.x * 8 + warp) * 8;
    if (rowbase >= NN) return;
    const float2* sWn2 = (const float2*)sWn;
    const float2* sWe2 = (const float2*)sWe;
    float xa[8], xb[8], xe[8], a0[8], a1[8];
#pragma unroll
    for (int r = 0; r < 8; r++) {
        int row = rowbase + r;
        bool v = row < NN;
        xa[r] = v ? nf[row * 64 + lane] : 0.f;
        xb[r] = v ? nf[row * 64 + lane + 32] : 0.f;
        xe[r] = (v && lane < 16) ? d_agg16[row * 16 + lane] : 0.f;
        a0[r] = 0.f;
        a1[r] = 0.f;
    }
#pragma unroll 4
    for (int k = 0; k < 64; k++) {
        float2 w = sWn2[k * 32 + lane];   // W[k][2*lane], W[k][2*lane+1]
#pragma unroll
        for (int r = 0; r < 8; r++) {
            float xk = __shfl_sync(0xffffffffu, (k < 32) ? xa[r] : xb[r], k & 31);
            a0[r] += xk * w.x;
            a1[r] += xk * w.y;
        }
    }
#pragma unroll 4
    for (int k = 0; k < 16; k++) {
        float2 w = sWe2[k * 32 + lane];
#pragma unroll
        for (int r = 0; r < 8; r++) {
            float xk = __shfl_sync(0xffffffffu, xe[r], k);
            a0[r] += xk * w.x;
            a1[r] += xk * w.y;
        }
    }
    float2 bn2 = ((const float2*)sbn)[lane];
    float2 be2 = ((const float2*)sbe)[lane];
    __half2* msg2 = (__half2*)d_msg;
    __half2* h2 = (__half2*)d_hA;
#pragma unroll
    for (int r = 0; r < 8; r++) {
        int row = rowbase + r;
        if (row >= NN) break;
        float deg = (float)(d_offsets[row + 1] - d_offsets[row]);
        float m0 = a0[r] + bn2.x + deg * be2.x;
        float m1 = a1[r] + bn2.y + deg * be2.y;
        msg2[row * 32 + lane] = __floats2half2_rn(m0, m1);
        h2[row * 32 + lane] = __floats2half2_rn(fmaxf(m0, 0.f), fmaxf(m1, 0.f));
    }
}

// ---------------- K5: fused level: h' = relu(segsum(h[src]) @ W + b + msg) ----------------
__global__ __launch_bounds__(512) void level_kernel(
    const float* __restrict__ Wc, const float* __restrict__ bc, int lv) {
    __shared__ float sW[4096];
    __shared__ float sb[64];
    int t = threadIdx.x;
#pragma unroll
    for (int i = t; i < 4096; i += 512) sW[i] = Wc[i];
    if (t < 64) sb[t] = bc[t];
    __syncthreads();
    int warp = t >> 5, lane = t & 31;
    int node = blockIdx.x * 16 + warp;
    if (node >= NN) return;
    const __half2* __restrict__ hin = (lv & 1) ? (const __half2*)d_hB : (const __half2*)d_hA;
    __half2* __restrict__ hout = (lv & 1) ? (__half2*)d_hA : (__half2*)d_hB;

    int s = d_offsets[node], e = d_offsets[node + 1];
    float2 acc0 = make_float2(0.f, 0.f), acc1 = make_float2(0.f, 0.f);
    float2 acc2 = make_float2(0.f, 0.f), acc3 = make_float2(0.f, 0.f);
    int p = s;
    for (; p + 4 <= e; p += 4) {
        int i0 = d_se[p].x, i1 = d_se[p + 1].x, i2 = d_se[p + 2].x, i3 = d_se[p + 3].x;
        __half2 v0 = hin[i0 * 32 + lane];
        __half2 v1 = hin[i1 * 32 + lane];
        __half2 v2 = hin[i2 * 32 + lane];
        __half2 v3 = hin[i3 * 32 + lane];
        float2 f0 = __half22float2(v0); acc0.x += f0.x; acc0.y += f0.y;
        float2 f1 = __half22float2(v1); acc1.x += f1.x; acc1.y += f1.y;
        float2 f2 = __half22float2(v2); acc2.x += f2.x; acc2.y += f2.y;
        float2 f3 = __half22float2(v3); acc3.x += f3.x; acc3.y += f3.y;
    }
    for (; p < e; p++) {
        float2 f = __half22float2(hin[d_se[p].x * 32 + lane]);
        acc0.x += f.x; acc0.y += f.y;
    }
    float x0 = (acc0.x + acc1.x) + (acc2.x + acc3.x);  // n2npool[2*lane]
    float x1 = (acc0.y + acc1.y) + (acc2.y + acc3.y);  // n2npool[2*lane+1]

    // o[j] = sum_k x[k] * W[k][j], for j = 2*lane, 2*lane+1
    float o0 = 0.f, o1 = 0.f;
    const float2* sW2 = (const float2*)sW;
#pragma unroll
    for (int kk = 0; kk < 32; kk++) {
        float xe0 = __shfl_sync(0xffffffffu, x0, kk);  // x[2*kk]
        float xe1 = __shfl_sync(0xffffffffu, x1, kk);  // x[2*kk+1]
        float2 wA = sW2[(2 * kk) * 32 + lane];
        float2 wB = sW2[(2 * kk + 1) * 32 + lane];
        o0 += xe0 * wA.x + xe1 * wB.x;
        o1 += xe0 * wA.y + xe1 * wB.y;
    }
    float2 mf = __half22float2(((const __half2*)d_msg)[node * 32 + lane]);
    float2 b2 = ((const float2*)sb)[lane];
    o0 = fmaxf(o0 + b2.x + mf.x, 0.f);
    o1 = fmaxf(o1 + b2.y + mf.y, 0.f);
    hout[node * 32 + lane] = __floats2half2_rn(o0, o1);
}

// ---------------- K7: out = relu(h@Wf + bf) -> graph sum-pool ----------------
__global__ __launch_bounds__(256) void final_kernel(
    const float* __restrict__ Wf, const float* __restrict__ bf,
    const int* __restrict__ gid, float* __restrict__ out) {
    __shared__ float sW[64 * 64];
    __shared__ float sb[64];
    const __half2* __restrict__ X = (const __half2*)d_hB;  // 3 levels -> ends in B
    int t = threadIdx.x;
    for (int i = t; i < 4096; i += 256) sW[i] = Wf[i];
    if (t < 64) sb[t] = bf[t];
    __syncthreads();
    int warp = t >> 5, lane = t & 31;
    int rowbase = (blockIdx.x * 8 + warp) * 8;
    if (rowbase >= NN) return;
    const float2* sW2 = (const float2*)sW;
    float2 bb = ((const float2*)sb)[lane];
    float xa0[8], xa1[8], a0[8], a1[8];
#pragma unroll
    for (int r = 0; r < 8; r++) {
        int row = rowbase + r;
        bool v = row < NN;
        float2 f = v ? __half22float2(X[row * 32 + lane]) : make_float2(0.f, 0.f);
        xa0[r] = f.x;   // x[2*lane]
        xa1[r] = f.y;   // x[2*lane+1]
        a0[r] = bb.x;
        a1[r] = bb.y;
    }
#pragma unroll 2
    for (int kk = 0; kk < 32; kk++) {
        float2 wA = sW2[(2 * kk) * 32 + lane];
        float2 wB = sW2[(2 * kk + 1) * 32 + lane];
#pragma unroll
        for (int r = 0; r < 8; r++) {
            float xk0 = __shfl_sync(0xffffffffu, xa0[r], kk);  // x[2*kk]
            float xk1 = __shfl_sync(0xffffffffu, xa1[r], kk);  // x[2*kk+1]
            a0[r] += xk0 * wA.x + xk1 * wB.x;
            a1[r] += xk0 * wA.y + xk1 * wB.y;
        }
    }
#pragma unroll
    for (int r = 0; r < 8; r++) {
        a0[r] = fmaxf(a0[r], 0.f);
        a1[r] = fmaxf(a1[r], 0.f);
    }
    bool full = (rowbase + 8 <= NN);
    int g0 = gid[rowbase];
    bool uni = full;
    if (full) {
#pragma unroll
        for (int r = 1; r < 8; r++) uni = uni && (gid[rowbase + r] == g0);
    }
    if (uni) {
        float s0 = 0.f, s1 = 0.f;
#pragma unroll
        for (int r = 0; r < 8; r++) { s0 += a0[r]; s1 += a1[r]; }
        atomicAdd(&out[g0 * 64 + 2 * lane], s0);
        atomicAdd(&out[g0 * 64 + 2 * lane + 1], s1);
    } else {
#pragma unroll
        for (int r = 0; r < 8; r++) {
            int row = rowbase + r;
            if (row >= NN) break;
            int gg = gid[row];
            atomicAdd(&out[gg * 64 + 2 * lane], a0[r]);
            atomicAdd(&out[gg * 64 + 2 * lane + 1], a1[r]);
        }
    }
}

// ---------------- host ----------------
extern "C" void kernel_launch(void* const* d_in, const int* in_sizes, int n_in,
                              void* d_out, int out_size) {
    const float *nf = 0, *ef = 0, *Wn = 0, *bn = 0, *We = 0, *be = 0;
    const float *Wc = 0, *bc = 0, *Wf = 0, *bf = 0;
    const int *esrc = 0, *edst = 0, *gid = 0;
    int n800 = 0, n4096 = 0, n64 = 0;
    for (int i = 0; i < n_in; i++) {
        int sz = in_sizes[i];
        const void* p = d_in[i];
        if (sz == NN * 64)      nf = (const float*)p;
        else if (sz == NE * 16) ef = (const float*)p;
        else if (sz == NE)      { if (n800++ == 0) esrc = (const int*)p; else edst = (const int*)p; }
        else if (sz == NN)      gid = (const int*)p;
        else if (sz == 4096)    { if (n4096++ == 0) Wn = (const float*)p; else Wf = (const float*)p; }
        else if (sz == 1024)    We = (const float*)p;
        else if (sz == 12288)   Wc = (const float*)p;
        else if (sz == 192)     bc = (const float*)p;
        else if (sz == 64)      { if (n64 == 0) bn = (const float*)p;
                                  else if (n64 == 1) be = (const float*)p;
                                  else bf = (const float*)p; n64++; }
    }
    float* out = (float*)d_out;

    zero_kernel<<<(NN + 255) / 256, 256>>>(out);
    hist_kernel<<<(NE + 255) / 256, 256>>>(edst);
    scan_kernel<<<1, 1024>>>();
    scatter_kernel<<<(NE / 4 + 255) / 256, 256>>>(esrc, edst);
    agg_edge_kernel<<<(NN + 7) / 8, 256>>>(ef);
    init_kernel<<<(NN + 63) / 64, 256>>>(nf, Wn, bn, We, be);
    for (int lv = 0; lv < 3; lv++)
        level_kernel<<<(NN + 15) / 16, 512>>>(Wc + lv * 4096, bc + lv * 64, lv);
    final_kernel<<<(NN + 63) / 64, 256>>>(Wf, bf, gid, out);
}

// round 3
// speedup vs baseline: 1.3001x; 1.2846x over previous
#include <cuda_runtime.h>
#include <cuda_fp16.h>

#define NN 50000
#define NE 800000
#define NG 128
#define FE 16
#define DD 64
#define NBLK ((NN + 255) / 256)   // 196 scan blocks

// ---------------- scratch (static device globals; no allocation) ----------------
__device__ int    d_counts[NN];
__device__ int    d_offsets[NN + 1];
__device__ int    d_cursor[NN];
__device__ int    d_bsum[NBLK];
__device__ int    d_bpre[NBLK + 1];
__device__ int2   d_se[NE];          // (src, eid) packed, CSR order by dst
__device__ float  d_agg16[NN * FE];
__device__ __half d_msg[NN * DD];
__device__ __half d_hA[NN * DD];
__device__ __half d_hB[NN * DD];

// ---------------- K0: zero output + histogram counters ----------------
__global__ void zero_kernel(float* __restrict__ out) {
    int i = blockIdx.x * blockDim.x + threadIdx.x;
    if (i < NG * DD) out[i] = 0.f;
    if (i < NN) d_counts[i] = 0;
}

// ---------------- K1: histogram of edge_dst ----------------
__global__ void hist_kernel(const int* __restrict__ dst) {
    int e = blockIdx.x * blockDim.x + threadIdx.x;
    if (e < NE) atomicAdd(&d_counts[dst[e]], 1);
}

// ---------------- K2a: per-block sums of counts (coalesced) ----------------
__global__ __launch_bounds__(256) void scan_partial_kernel() {
    __shared__ int sm[256];
    int t = threadIdx.x;
    int i = blockIdx.x * 256 + t;
    int v = (i < NN) ? d_counts[i] : 0;
    sm[t] = v;
    __syncthreads();
#pragma unroll
    for (int d = 128; d > 0; d >>= 1) {
        if (t < d) sm[t] += sm[t + d];
        __syncthreads();
    }
    if (t == 0) d_bsum[blockIdx.x] = sm[0];
}

// ---------------- K2b: scan the 196 block sums (one tiny block) ----------------
__global__ __launch_bounds__(256) void scan_mid_kernel() {
    __shared__ int sm[256];
    int t = threadIdx.x;
    int v = (t < NBLK) ? d_bsum[t] : 0;
    sm[t] = v;
    __syncthreads();
#pragma unroll
    for (int d = 1; d < 256; d <<= 1) {
        int x = (t >= d) ? sm[t - d] : 0;
        __syncthreads();
        sm[t] += x;
        __syncthreads();
    }
    d_bpre[t < NBLK ? t : NBLK] = (t == 0) ? 0 : sm[t - 1];
    if (t == 255) d_offsets[NN] = sm[255];
}

// ---------------- K2c: local exclusive scan + block prefix -> offsets/cursor ----------------
__global__ __launch_bounds__(256) void scan_final_kernel() {
    __shared__ int sm[256];
    int b = blockIdx.x, t = threadIdx.x;
    int i = b * 256 + t;
    int v = (i < NN) ? d_counts[i] : 0;
    sm[t] = v;
    __syncthreads();
#pragma unroll
    for (int d = 1; d < 256; d <<= 1) {
        int x = (t >= d) ? sm[t - d] : 0;
        __syncthreads();
        sm[t] += x;
        __syncthreads();
    }
    if (i < NN) {
        int excl = sm[t] - v + d_bpre[b];
        d_offsets[i] = excl;
        d_cursor[i] = excl;
    }
}

// ---------------- K3: scatter edges into CSR order (4 edges/thread, int2 stores) ----------------
__global__ void scatter_kernel(const int* __restrict__ src, const int* __restrict__ dst) {
    int base = (blockIdx.x * blockDim.x + threadIdx.x) * 4;
#pragma unroll
    for (int j = 0; j < 4; j++) {
        int e = base + j;
        if (e < NE) {
            int dn = dst[e];
            int p = atomicAdd(&d_cursor[dn], 1);
            d_se[p] = make_int2(src[e], e);
        }
    }
}

// ---------------- K4a: per-node sum of incident edge features (16-dim) ----------------
__global__ __launch_bounds__(256) void agg_edge_kernel(const float* __restrict__ ef) {
    int node = blockIdx.x * 8 + (threadIdx.x >> 5);
    if (node >= NN) return;
    int lane = threadIdx.x & 31;
    int s = d_offsets[node], e = d_offsets[node + 1];
    int f = lane & 15, half = lane >> 4;
    float acc0 = 0.f, acc1 = 0.f;
    int p = s + half;
    for (; p + 2 < e; p += 4) {
        int e0 = d_se[p].y;
        int e1 = d_se[p + 2].y;
        acc0 += ef[e0 * FE + f];
        acc1 += ef[e1 * FE + f];
    }
    if (p < e) acc0 += ef[d_se[p].y * FE + f];
    float acc = acc0 + acc1;
    acc += __shfl_xor_sync(0xffffffffu, acc, 16);
    if (lane < 16) d_agg16[node * FE + lane] = acc;
}

// ---------------- K4b: msg = nf@Wn + bn + agg16@We + deg*be ; h0 = relu(msg) (fp16 out) ----------------
__global__ __launch_bounds__(256) void init_kernel(
    const float* __restrict__ nf, const float* __restrict__ Wn, const float* __restrict__ bn,
    const float* __restrict__ We, const float* __restrict__ be) {
    __shared__ float sWn[64 * 64];
    __shared__ float sWe[16 * 64];
    __shared__ float sbn[64], sbe[64];
    int t = threadIdx.x;
    for (int i = t; i < 64 * 64; i += 256) sWn[i] = Wn[i];
    for (int i = t; i < 16 * 64; i += 256) sWe[i] = We[i];
    if (t < 64) { sbn[t] = bn[t]; sbe[t] = be[t]; }
    __syncthreads();
    int warp = t >> 5, lane = t & 31;
    int rowbase = (blockIdx.x * 8 + warp) * 8;
    if (rowbase >= NN) return;
    const float2* sWn2 = (const float2*)sWn;
    const float2* sWe2 = (const float2*)sWe;
    float xa[8], xb[8], xe[8], a0[8], a1[8];
#pragma unroll
    for (int r = 0; r < 8; r++) {
        int row = rowbase + r;
        bool v = row < NN;
        xa[r] = v ? nf[row * 64 + lane] : 0.f;
        xb[r] = v ? nf[row * 64 + lane + 32] : 0.f;
        xe[r] = (v && lane < 16) ? d_agg16[row * 16 + lane] : 0.f;
        a0[r] = 0.f;
        a1[r] = 0.f;
    }
#pragma unroll 4
    for (int k = 0; k < 64; k++) {
        float2 w = sWn2[k * 32 + lane];
#pragma unroll
        for (int r = 0; r < 8; r++) {
            float xk = __shfl_sync(0xffffffffu, (k < 32) ? xa[r] : xb[r], k & 31);
            a0[r] += xk * w.x;
            a1[r] += xk * w.y;
        }
    }
#pragma unroll 4
    for (int k = 0; k < 16; k++) {
        float2 w = sWe2[k * 32 + lane];
#pragma unroll
        for (int r = 0; r < 8; r++) {
            float xk = __shfl_sync(0xffffffffu, xe[r], k);
            a0[r] += xk * w.x;
            a1[r] += xk * w.y;
        }
    }
    float2 bn2 = ((const float2*)sbn)[lane];
    float2 be2 = ((const float2*)sbe)[lane];
    __half2* msg2 = (__half2*)d_msg;
    __half2* h2 = (__half2*)d_hA;
#pragma unroll
    for (int r = 0; r < 8; r++) {
        int row = rowbase + r;
        if (row >= NN) break;
        float deg = (float)(d_offsets[row + 1] - d_offsets[row]);
        float m0 = a0[r] + bn2.x + deg * be2.x;
        float m1 = a1[r] + bn2.y + deg * be2.y;
        msg2[row * 32 + lane] = __floats2half2_rn(m0, m1);
        h2[row * 32 + lane] = __floats2half2_rn(fmaxf(m0, 0.f), fmaxf(m1, 0.f));
    }
}

// ---------------- K5: fused level: h' = relu(segsum(h[src]) @ W + b + msg) ----------------
__global__ __launch_bounds__(512) void level_kernel(
    const float* __restrict__ Wc, const float* __restrict__ bc, int lv) {
    __shared__ float sW[4096];
    __shared__ float sb[64];
    int t = threadIdx.x;
#pragma unroll
    for (int i = t; i < 4096; i += 512) sW[i] = Wc[i];
    if (t < 64) sb[t] = bc[t];
    __syncthreads();
    int warp = t >> 5, lane = t & 31;
    int node = blockIdx.x * 16 + warp;
    if (node >= NN) return;
    const __half2* __restrict__ hin = (lv & 1) ? (const __half2*)d_hB : (const __half2*)d_hA;
    __half2* __restrict__ hout = (lv & 1) ? (__half2*)d_hA : (__half2*)d_hB;

    int s = d_offsets[node], e = d_offsets[node + 1];
    float2 acc0 = make_float2(0.f, 0.f), acc1 = make_float2(0.f, 0.f);
    float2 acc2 = make_float2(0.f, 0.f), acc3 = make_float2(0.f, 0.f);
    int p = s;
    for (; p + 4 <= e; p += 4) {
        int i0 = d_se[p].x, i1 = d_se[p + 1].x, i2 = d_se[p + 2].x, i3 = d_se[p + 3].x;
        __half2 v0 = hin[i0 * 32 + lane];
        __half2 v1 = hin[i1 * 32 + lane];
        __half2 v2 = hin[i2 * 32 + lane];
        __half2 v3 = hin[i3 * 32 + lane];
        float2 f0 = __half22float2(v0); acc0.x += f0.x; acc0.y += f0.y;
        float2 f1 = __half22float2(v1); acc1.x += f1.x; acc1.y += f1.y;
        float2 f2 = __half22float2(v2); acc2.x += f2.x; acc2.y += f2.y;
        float2 f3 = __half22float2(v3); acc3.x += f3.x; acc3.y += f3.y;
    }
    for (; p < e; p++) {
        float2 f = __half22float2(hin[d_se[p].x * 32 + lane]);
        acc0.x += f.x; acc0.y += f.y;
    }
    float x0 = (acc0.x + acc1.x) + (acc2.x + acc3.x);
    float x1 = (acc0.y + acc1.y) + (acc2.y + acc3.y);

    float o0 = 0.f, o1 = 0.f;
    const float2* sW2 = (const float2*)sW;
#pragma unroll
    for (int kk = 0; kk < 32; kk++) {
        float xe0 = __shfl_sync(0xffffffffu, x0, kk);
        float xe1 = __shfl_sync(0xffffffffu, x1, kk);
        float2 wA = sW2[(2 * kk) * 32 + lane];
        float2 wB = sW2[(2 * kk + 1) * 32 + lane];
        o0 += xe0 * wA.x + xe1 * wB.x;
        o1 += xe0 * wA.y + xe1 * wB.y;
    }
    float2 mf = __half22float2(((const __half2*)d_msg)[node * 32 + lane]);
    float2 b2 = ((const float2*)sb)[lane];
    o0 = fmaxf(o0 + b2.x + mf.x, 0.f);
    o1 = fmaxf(o1 + b2.y + mf.y, 0.f);
    hout[node * 32 + lane] = __floats2half2_rn(o0, o1);
}

// ---------------- K7: out = relu(h@Wf + bf) -> graph sum-pool ----------------
__global__ __launch_bounds__(256) void final_kernel(
    const float* __restrict__ Wf, const float* __restrict__ bf,
    const int* __restrict__ gid, float* __restrict__ out) {
    __shared__ float sW[64 * 64];
    __shared__ float sb[64];
    const __half2* __restrict__ X = (const __half2*)d_hB;  // 3 levels -> ends in B
    int t = threadIdx.x;
    for (int i = t; i < 4096; i += 256) sW[i] = Wf[i];
    if (t < 64) sb[t] = bf[t];
    __syncthreads();
    int warp = t >> 5, lane = t & 31;
    int rowbase = (blockIdx.x * 8 + warp) * 8;
    if (rowbase >= NN) return;
    const float2* sW2 = (const float2*)sW;
    float2 bb = ((const float2*)sb)[lane];
    float xa0[8], xa1[8], a0[8], a1[8];
#pragma unroll
    for (int r = 0; r < 8; r++) {
        int row = rowbase + r;
        bool v = row < NN;
        float2 f = v ? __half22float2(X[row * 32 + lane]) : make_float2(0.f, 0.f);
        xa0[r] = f.x;
        xa1[r] = f.y;
        a0[r] = bb.x;
        a1[r] = bb.y;
    }
#pragma unroll 2
    for (int kk = 0; kk < 32; kk++) {
        float2 wA = sW2[(2 * kk) * 32 + lane];
        float2 wB = sW2[(2 * kk + 1) * 32 + lane];
#pragma unroll
        for (int r = 0; r < 8; r++) {
            float xk0 = __shfl_sync(0xffffffffu, xa0[r], kk);
            float xk1 = __shfl_sync(0xffffffffu, xa1[r], kk);
            a0[r] += xk0 * wA.x + xk1 * wB.x;
            a1[r] += xk0 * wA.y + xk1 * wB.y;
        }
    }
#pragma unroll
    for (int r = 0; r < 8; r++) {
        a0[r] = fmaxf(a0[r], 0.f);
        a1[r] = fmaxf(a1[r], 0.f);
    }
    bool full = (rowbase + 8 <= NN);
    int g0 = gid[rowbase];
    bool uni = full;
    if (full) {
#pragma unroll
        for (int r = 1; r < 8; r++) uni = uni && (gid[rowbase + r] == g0);
    }
    if (uni) {
        float s0 = 0.f, s1 = 0.f;
#pragma unroll
        for (int r = 0; r < 8; r++) { s0 += a0[r]; s1 += a1[r]; }
        atomicAdd(&out[g0 * 64 + 2 * lane], s0);
        atomicAdd(&out[g0 * 64 + 2 * lane + 1], s1);
    } else {
#pragma unroll
        for (int r = 0; r < 8; r++) {
            int row = rowbase + r;
            if (row >= NN) break;
            int gg = gid[row];
            atomicAdd(&out[gg * 64 + 2 * lane], a0[r]);
            atomicAdd(&out[gg * 64 + 2 * lane + 1], a1[r]);
        }
    }
}

// ---------------- host ----------------
extern "C" void kernel_launch(void* const* d_in, const int* in_sizes, int n_in,
                              void* d_out, int out_size) {
    const float *nf = 0, *ef = 0, *Wn = 0, *bn = 0, *We = 0, *be = 0;
    const float *Wc = 0, *bc = 0, *Wf = 0, *bf = 0;
    const int *esrc = 0, *edst = 0, *gid = 0;
    int n800 = 0, n4096 = 0, n64 = 0;
    for (int i = 0; i < n_in; i++) {
        int sz = in_sizes[i];
        const void* p = d_in[i];
        if (sz == NN * 64)      nf = (const float*)p;
        else if (sz == NE * 16) ef = (const float*)p;
        else if (sz == NE)      { if (n800++ == 0) esrc = (const int*)p; else edst = (const int*)p; }
        else if (sz == NN)      gid = (const int*)p;
        else if (sz == 4096)    { if (n4096++ == 0) Wn = (const float*)p; else Wf = (const float*)p; }
        else if (sz == 1024)    We = (const float*)p;
        else if (sz == 12288)   Wc = (const float*)p;
        else if (sz == 192)     bc = (const float*)p;
        else if (sz == 64)      { if (n64 == 0) bn = (const float*)p;
                                  else if (n64 == 1) be = (const float*)p;
                                  else bf = (const float*)p; n64++; }
    }
    float* out = (float*)d_out;

    zero_kernel<<<(NN + 255) / 256, 256>>>(out);
    hist_kernel<<<(NE + 255) / 256, 256>>>(edst);
    scan_partial_kernel<<<NBLK, 256>>>();
    scan_mid_kernel<<<1, 256>>>();
    scan_final_kernel<<<NBLK, 256>>>();
    scatter_kernel<<<(NE / 4 + 255) / 256, 256>>>(esrc, edst);
    agg_edge_kernel<<<(NN + 7) / 8, 256>>>(ef);
    init_kernel<<<(NN + 63) / 64, 256>>>(nf, Wn, bn, We, be);
    for (int lv = 0; lv < 3; lv++)
        level_kernel<<<(NN + 15) / 16, 512>>>(Wc + lv * 4096, bc + lv * 64, lv);
    final_kernel<<<(NN + 63) / 64, 256>>>(Wf, bf, gid, out);
}

// round 4
// speedup vs baseline: 1.3103x; 1.0079x over previous
#include <cuda_runtime.h>
#include <cuda_fp16.h>

#define NN 50000
#define NE 800000
#define NG 128
#define FE 16
#define DD 64
#define NBLK ((NN + 255) / 256)   // 196 scan blocks

// ---------------- scratch (static device globals; no allocation) ----------------
__device__ int    d_counts[NN];
__device__ int    d_offsets[NN + 1];
__device__ int    d_rank[NE];
__device__ unsigned long long d_scanstate[NBLK];
__device__ int2   d_se[NE];          // (src, eid) packed, CSR order by dst
__device__ float  d_agg16[NN * FE];
__device__ __half d_msg[NN * DD];
__device__ __half d_hA[NN * DD];
__device__ __half d_hB[NN * DD];

// ---------------- K0: zero output + counters + scan state ----------------
__global__ void zero_kernel(float* __restrict__ out) {
    int i = blockIdx.x * blockDim.x + threadIdx.x;
    if (i < NG * DD) out[i] = 0.f;
    if (i < NN) d_counts[i] = 0;
    if (i < NBLK) d_scanstate[i] = 0ULL;
    if (i == 0) d_offsets[NN] = NE;
}

// ---------------- K1: histogram of edge_dst; atomic return = rank within bucket ----------------
__global__ void hist_kernel(const int* __restrict__ dst) {
    int e = blockIdx.x * blockDim.x + threadIdx.x;
    if (e < NE) d_rank[e] = atomicAdd(&d_counts[dst[e]], 1);
}

// ---------------- K2: single-pass decoupled-lookback exclusive scan -> offsets ----------------
__global__ __launch_bounds__(256) void scan_kernel() {
    __shared__ int sm[256];
    __shared__ int s_excl;
    int b = blockIdx.x, t = threadIdx.x;
    int i = b * 256 + t;
    int v = (i < NN) ? d_counts[i] : 0;
    sm[t] = v;
    __syncthreads();
#pragma unroll
    for (int d = 1; d < 256; d <<= 1) {
        int x = (t >= d) ? sm[t - d] : 0;
        __syncthreads();
        sm[t] += x;
        __syncthreads();
    }
    int incl = sm[t];
    int agg = sm[255];
    if (t == 0) {
        unsigned long long fl = (b == 0) ? 2ULL : 1ULL;
        atomicExch(&d_scanstate[b], (fl << 32) | (unsigned long long)(unsigned)agg);
        if (b == 0) s_excl = 0;
    }
    if (b > 0 && t < 32) {
        int lane = t;
        int j = b - 1;
        int excl = 0;
        while (true) {
            int idx = j - lane;
            unsigned long long s;
            if (idx >= 0) {
                do { s = atomicAdd(&d_scanstate[idx], 0ULL); } while ((s >> 32) == 0ULL);
            } else {
                s = (2ULL << 32);  // virtual prefix 0 before block 0
            }
            unsigned fl = (unsigned)(s >> 32);
            int val = (int)(unsigned)(s & 0xffffffffULL);
            unsigned mask = __ballot_sync(0xffffffffu, fl == 2u);
            if (mask) {
                int lmin = __ffs(mask) - 1;
                int contrib = (lane <= lmin) ? val : 0;
#pragma unroll
                for (int o = 16; o > 0; o >>= 1) contrib += __shfl_down_sync(0xffffffffu, contrib, o);
                contrib = __shfl_sync(0xffffffffu, contrib, 0);
                excl += contrib;
                break;
            } else {
                int contrib = val;
#pragma unroll
                for (int o = 16; o > 0; o >>= 1) contrib += __shfl_down_sync(0xffffffffu, contrib, o);
                contrib = __shfl_sync(0xffffffffu, contrib, 0);
                excl += contrib;
                j -= 32;
            }
        }
        if (lane == 0) {
            atomicExch(&d_scanstate[b], (2ULL << 32) | (unsigned long long)(unsigned)(excl + agg));
            s_excl = excl;
        }
    }
    __syncthreads();
    if (i < NN) d_offsets[i] = s_excl + incl - v;
}

// ---------------- K3: scatter edges into CSR order (atomic-free) ----------------
__global__ void scatter_kernel(const int* __restrict__ src, const int* __restrict__ dst) {
    int e = blockIdx.x * blockDim.x + threadIdx.x;
    if (e < NE) {
        int dn = dst[e];
        int p = d_offsets[dn] + d_rank[e];
        d_se[p] = make_int2(src[e], e);
    }
}

// ---------------- K4a: per-node sum of incident edge features (16-dim) ----------------
__global__ __launch_bounds__(256) void agg_edge_kernel(const float* __restrict__ ef) {
    int node = blockIdx.x * 8 + (threadIdx.x >> 5);
    if (node >= NN) return;
    int lane = threadIdx.x & 31;
    int s = d_offsets[node], e = d_offsets[node + 1];
    int f = lane & 15, half = lane >> 4;
    float acc0 = 0.f, acc1 = 0.f;
    int p = s + half;
    for (; p + 2 < e; p += 4) {
        int e0 = d_se[p].y;
        int e1 = d_se[p + 2].y;
        acc0 += ef[e0 * FE + f];
        acc1 += ef[e1 * FE + f];
    }
    if (p < e) acc0 += ef[d_se[p].y * FE + f];
    float acc = acc0 + acc1;
    acc += __shfl_xor_sync(0xffffffffu, acc, 16);
    if (lane < 16) d_agg16[node * FE + lane] = acc;
}

// ---------------- K4b: msg = nf@Wn + bn + agg16@We + deg*be ; h0 = relu(msg) (fp16 out) ----------------
__global__ __launch_bounds__(256) void init_kernel(
    const float* __restrict__ nf, const float* __restrict__ Wn, const float* __restrict__ bn,
    const float* __restrict__ We, const float* __restrict__ be) {
    __shared__ float sWn[64 * 64];
    __shared__ float sWe[16 * 64];
    __shared__ float sbn[64], sbe[64];
    int t = threadIdx.x;
    for (int i = t; i < 64 * 64; i += 256) sWn[i] = Wn[i];
    for (int i = t; i < 16 * 64; i += 256) sWe[i] = We[i];
    if (t < 64) { sbn[t] = bn[t]; sbe[t] = be[t]; }
    __syncthreads();
    int warp = t >> 5, lane = t & 31;
    int rowbase = (blockIdx.x * 8 + warp) * 8;
    if (rowbase >= NN) return;
    const float2* sWn2 = (const float2*)sWn;
    const float2* sWe2 = (const float2*)sWe;
    float xa[8], xb[8], xe[8], a0[8], a1[8];
#pragma unroll
    for (int r = 0; r < 8; r++) {
        int row = rowbase + r;
        bool v = row < NN;
        xa[r] = v ? nf[row * 64 + lane] : 0.f;
        xb[r] = v ? nf[row * 64 + lane + 32] : 0.f;
        xe[r] = (v && lane < 16) ? d_agg16[row * 16 + lane] : 0.f;
        a0[r] = 0.f;
        a1[r] = 0.f;
    }
#pragma unroll 4
    for (int k = 0; k < 64; k++) {
        float2 w = sWn2[k * 32 + lane];
#pragma unroll
        for (int r = 0; r < 8; r++) {
            float xk = __shfl_sync(0xffffffffu, (k < 32) ? xa[r] : xb[r], k & 31);
            a0[r] += xk * w.x;
            a1[r] += xk * w.y;
        }
    }
#pragma unroll 4
    for (int k = 0; k < 16; k++) {
        float2 w = sWe2[k * 32 + lane];
#pragma unroll
        for (int r = 0; r < 8; r++) {
            float xk = __shfl_sync(0xffffffffu, xe[r], k);
            a0[r] += xk * w.x;
            a1[r] += xk * w.y;
        }
    }
    float2 bn2 = ((const float2*)sbn)[lane];
    float2 be2 = ((const float2*)sbe)[lane];
    __half2* msg2 = (__half2*)d_msg;
    __half2* h2 = (__half2*)d_hA;
#pragma unroll
    for (int r = 0; r < 8; r++) {
        int row = rowbase + r;
        if (row >= NN) break;
        float deg = (float)(d_offsets[row + 1] - d_offsets[row]);
        float m0 = a0[r] + bn2.x + deg * be2.x;
        float m1 = a1[r] + bn2.y + deg * be2.y;
        msg2[row * 32 + lane] = __floats2half2_rn(m0, m1);
        h2[row * 32 + lane] = __floats2half2_rn(fmaxf(m0, 0.f), fmaxf(m1, 0.f));
    }
}

// ---------------- K5: fused level: h' = relu(segsum(h[src]) @ W + b + msg) ----------------
__global__ __launch_bounds__(512) void level_kernel(
    const float* __restrict__ Wc, const float* __restrict__ bc, int lv) {
    __shared__ float sW[4096];
    __shared__ float sb[64];
    int t = threadIdx.x;
#pragma unroll
    for (int i = t; i < 4096; i += 512) sW[i] = Wc[i];
    if (t < 64) sb[t] = bc[t];
    __syncthreads();
    int warp = t >> 5, lane = t & 31;
    int node = blockIdx.x * 16 + warp;
    if (node >= NN) return;
    const __half2* __restrict__ hin = (lv & 1) ? (const __half2*)d_hB : (const __half2*)d_hA;
    __half2* __restrict__ hout = (lv & 1) ? (__half2*)d_hA : (__half2*)d_hB;

    int s = d_offsets[node], e = d_offsets[node + 1];
    float2 acc0 = make_float2(0.f, 0.f), acc1 = make_float2(0.f, 0.f);
    float2 acc2 = make_float2(0.f, 0.f), acc3 = make_float2(0.f, 0.f);
    int p = s;
    for (; p + 4 <= e; p += 4) {
        int i0 = d_se[p].x, i1 = d_se[p + 1].x, i2 = d_se[p + 2].x, i3 = d_se[p + 3].x;
        __half2 v0 = hin[i0 * 32 + lane];
        __half2 v1 = hin[i1 * 32 + lane];
        __half2 v2 = hin[i2 * 32 + lane];
        __half2 v3 = hin[i3 * 32 + lane];
        float2 f0 = __half22float2(v0); acc0.x += f0.x; acc0.y += f0.y;
        float2 f1 = __half22float2(v1); acc1.x += f1.x; acc1.y += f1.y;
        float2 f2 = __half22float2(v2); acc2.x += f2.x; acc2.y += f2.y;
        float2 f3 = __half22float2(v3); acc3.x += f3.x; acc3.y += f3.y;
    }
    for (; p < e; p++) {
        float2 f = __half22float2(hin[d_se[p].x * 32 + lane]);
        acc0.x += f.x; acc0.y += f.y;
    }
    float x0 = (acc0.x + acc1.x) + (acc2.x + acc3.x);
    float x1 = (acc0.y + acc1.y) + (acc2.y + acc3.y);

    float o0 = 0.f, o1 = 0.f;
    const float2* sW2 = (const float2*)sW;
#pragma unroll
    for (int kk = 0; kk < 32; kk++) {
        float xe0 = __shfl_sync(0xffffffffu, x0, kk);
        float xe1 = __shfl_sync(0xffffffffu, x1, kk);
        float2 wA = sW2[(2 * kk) * 32 + lane];
        float2 wB = sW2[(2 * kk + 1) * 32 + lane];
        o0 += xe0 * wA.x + xe1 * wB.x;
        o1 += xe0 * wA.y + xe1 * wB.y;
    }
    float2 mf = __half22float2(((const __half2*)d_msg)[node * 32 + lane]);
    float2 b2 = ((const float2*)sb)[lane];
    o0 = fmaxf(o0 + b2.x + mf.x, 0.f);
    o1 = fmaxf(o1 + b2.y + mf.y, 0.f);
    hout[node * 32 + lane] = __floats2half2_rn(o0, o1);
}

// ---------------- K7: out = relu(h@Wf + bf) -> graph sum-pool ----------------
__global__ __launch_bounds__(256) void final_kernel(
    const float* __restrict__ Wf, const float* __restrict__ bf,
    const int* __restrict__ gid, float* __restrict__ out) {
    __shared__ float sW[64 * 64];
    __shared__ float sb[64];
    const __half2* __restrict__ X = (const __half2*)d_hB;  // 3 levels -> ends in B
    int t = threadIdx.x;
    for (int i = t; i < 4096; i += 256) sW[i] = Wf[i];
    if (t < 64) sb[t] = bf[t];
    __syncthreads();
    int warp = t >> 5, lane = t & 31;
    int rowbase = (blockIdx.x * 8 + warp) * 8;
    if (rowbase >= NN) return;
    const float2* sW2 = (const float2*)sW;
    float2 bb = ((const float2*)sb)[lane];
    float xa0[8], xa1[8], a0[8], a1[8];
#pragma unroll
    for (int r = 0; r < 8; r++) {
        int row = rowbase + r;
        bool v = row < NN;
        float2 f = v ? __half22float2(X[row * 32 + lane]) : make_float2(0.f, 0.f);
        xa0[r] = f.x;
        xa1[r] = f.y;
        a0[r] = bb.x;
        a1[r] = bb.y;
    }
#pragma unroll 2
    for (int kk = 0; kk < 32; kk++) {
        float2 wA = sW2[(2 * kk) * 32 + lane];
        float2 wB = sW2[(2 * kk + 1) * 32 + lane];
#pragma unroll
        for (int r = 0; r < 8; r++) {
            float xk0 = __shfl_sync(0xffffffffu, xa0[r], kk);
            float xk1 = __shfl_sync(0xffffffffu, xa1[r], kk);
            a0[r] += xk0 * wA.x + xk1 * wB.x;
            a1[r] += xk0 * wA.y + xk1 * wB.y;
        }
    }
#pragma unroll
    for (int r = 0; r < 8; r++) {
        a0[r] = fmaxf(a0[r], 0.f);
        a1[r] = fmaxf(a1[r], 0.f);
    }
    bool full = (rowbase + 8 <= NN);
    int g0 = gid[rowbase];
    bool uni = full;
    if (full) {
#pragma unroll
        for (int r = 1; r < 8; r++) uni = uni && (gid[rowbase + r] == g0);
    }
    if (uni) {
        float s0 = 0.f, s1 = 0.f;
#pragma unroll
        for (int r = 0; r < 8; r++) { s0 += a0[r]; s1 += a1[r]; }
        atomicAdd(&out[g0 * 64 + 2 * lane], s0);
        atomicAdd(&out[g0 * 64 + 2 * lane + 1], s1);
    } else {
#pragma unroll
        for (int r = 0; r < 8; r++) {
            int row = rowbase + r;
            if (row >= NN) break;
            int gg = gid[row];
            atomicAdd(&out[gg * 64 + 2 * lane], a0[r]);
            atomicAdd(&out[gg * 64 + 2 * lane + 1], a1[r]);
        }
    }
}

// ---------------- host ----------------
extern "C" void kernel_launch(void* const* d_in, const int* in_sizes, int n_in,
                              void* d_out, int out_size) {
    const float *nf = 0, *ef = 0, *Wn = 0, *bn = 0, *We = 0, *be = 0;
    const float *Wc = 0, *bc = 0, *Wf = 0, *bf = 0;
    const int *esrc = 0, *edst = 0, *gid = 0;
    int n800 = 0, n4096 = 0, n64 = 0;
    for (int i = 0; i < n_in; i++) {
        int sz = in_sizes[i];
        const void* p = d_in[i];
        if (sz == NN * 64)      nf = (const float*)p;
        else if (sz == NE * 16) ef = (const float*)p;
        else if (sz == NE)      { if (n800++ == 0) esrc = (const int*)p; else edst = (const int*)p; }
        else if (sz == NN)      gid = (const int*)p;
        else if (sz == 4096)    { if (n4096++ == 0) Wn = (const float*)p; else Wf = (const float*)p; }
        else if (sz == 1024)    We = (const float*)p;
        else if (sz == 12288)   Wc = (const float*)p;
        else if (sz == 192)     bc = (const float*)p;
        else if (sz == 64)      { if (n64 == 0) bn = (const float*)p;
                                  else if (n64 == 1) be = (const float*)p;
                                  else bf = (const float*)p; n64++; }
    }
    float* out = (float*)d_out;

    zero_kernel<<<(NN + 255) / 256, 256>>>(out);
    hist_kernel<<<(NE + 255) / 256, 256>>>(edst);
    scan_kernel<<<NBLK, 256>>>();
    scatter_kernel<<<(NE + 255) / 256, 256>>>(esrc, edst);
    agg_edge_kernel<<<(NN + 7) / 8, 256>>>(ef);
    init_kernel<<<(NN + 63) / 64, 256>>>(nf, Wn, bn, We, be);
    for (int lv = 0; lv < 3; lv++)
        level_kernel<<<(NN + 15) / 16, 512>>>(Wc + lv * 4096, bc + lv * 64, lv);
    final_kernel<<<(NN + 63) / 64, 256>>>(Wf, bf, gid, out);
}

// round 5
// speedup vs baseline: 1.8956x; 1.4466x over previous
#include <cuda_runtime.h>
#include <cuda_fp16.h>
#include <cstdint>

#define NN 50000
#define NNPAD 50048           // 782 * 64
#define NE 800000
#define NG 128
#define FE 16
#define DD 64
#define NBLK ((NN + 255) / 256)   // 196 scan blocks

// ---------------- scratch (static device globals; no allocation) ----------------
__device__ int    d_counts[NN];
__device__ int    d_offsets[NN + 1];
__device__ int    d_rank[NE];
__device__ unsigned long long d_scanstate[NBLK];
__device__ int2   d_se[NE];          // (src, eid) packed, CSR order by dst
__device__ float  d_agg16[NNPAD * FE];
__device__ __half d_msg[NNPAD * DD];
__device__ __half d_hA[NNPAD * DD];
__device__ __half d_hB[NNPAD * DD];
__device__ __half d_g[NNPAD * DD];
__device__ __half d_Wni[80 * 64];    // rows 0-63: W_n2l, rows 64-79: W_e2l
__device__ __half d_Wc16[3 * 64 * 64];

__device__ __forceinline__ uint32_t smem_u32(const void* p) {
    return (uint32_t)__cvta_generic_to_shared(p);
}

// ---------------- K0: zero output/counters/scanstate + convert weights to fp16 ----------------
__global__ void zero_kernel(float* __restrict__ out, const float* __restrict__ Wn,
                            const float* __restrict__ We, const float* __restrict__ Wc) {
    int i = blockIdx.x * blockDim.x + threadIdx.x;
    if (i < NG * DD) out[i] = 0.f;
    if (i < NN) d_counts[i] = 0;
    if (i < NBLK) d_scanstate[i] = 0ULL;
    if (i == 0) d_offsets[NN] = NE;
    if (i < 4096) d_Wni[i] = __float2half(Wn[i]);
    else if (i < 5120) d_Wni[i] = __float2half(We[i - 4096]);
    if (i < 12288) d_Wc16[i] = __float2half(Wc[i]);
}

// ---------------- K1: histogram of edge_dst; atomic return = rank within bucket ----------------
__global__ void hist_kernel(const int* __restrict__ dst) {
    int e = blockIdx.x * blockDim.x + threadIdx.x;
    if (e < NE) d_rank[e] = atomicAdd(&d_counts[dst[e]], 1);
}

// ---------------- K2: single-pass decoupled-lookback exclusive scan -> offsets ----------------
__global__ __launch_bounds__(256) void scan_kernel() {
    __shared__ int sm[256];
    __shared__ int s_excl;
    int b = blockIdx.x, t = threadIdx.x;
    int i = b * 256 + t;
    int v = (i < NN) ? d_counts[i] : 0;
    sm[t] = v;
    __syncthreads();
#pragma unroll
    for (int d = 1; d < 256; d <<= 1) {
        int x = (t >= d) ? sm[t - d] : 0;
        __syncthreads();
        sm[t] += x;
        __syncthreads();
    }
    int incl = sm[t];
    int agg = sm[255];
    if (t == 0) {
        unsigned long long fl = (b == 0) ? 2ULL : 1ULL;
        atomicExch(&d_scanstate[b], (fl << 32) | (unsigned long long)(unsigned)agg);
        if (b == 0) s_excl = 0;
    }
    if (b > 0 && t < 32) {
        int lane = t;
        int j = b - 1;
        int excl = 0;
        while (true) {
            int idx = j - lane;
            unsigned long long s;
            if (idx >= 0) {
                do { s = atomicAdd(&d_scanstate[idx], 0ULL); } while ((s >> 32) == 0ULL);
            } else {
                s = (2ULL << 32);
            }
            unsigned fl = (unsigned)(s >> 32);
            int val = (int)(unsigned)(s & 0xffffffffULL);
            unsigned mask = __ballot_sync(0xffffffffu, fl == 2u);
            if (mask) {
                int lmin = __ffs(mask) - 1;
                int contrib = (lane <= lmin) ? val : 0;
#pragma unroll
                for (int o = 16; o > 0; o >>= 1) contrib += __shfl_down_sync(0xffffffffu, contrib, o);
                contrib = __shfl_sync(0xffffffffu, contrib, 0);
                excl += contrib;
                break;
            } else {
                int contrib = val;
#pragma unroll
                for (int o = 16; o > 0; o >>= 1) contrib += __shfl_down_sync(0xffffffffu, contrib, o);
                contrib = __shfl_sync(0xffffffffu, contrib, 0);
                excl += contrib;
                j -= 32;
            }
        }
        if (lane == 0) {
            atomicExch(&d_scanstate[b], (2ULL << 32) | (unsigned long long)(unsigned)(excl + agg));
            s_excl = excl;
        }
    }
    __syncthreads();
    if (i < NN) d_offsets[i] = s_excl + incl - v;
}

// ---------------- K3: scatter edges into CSR order (atomic-free) ----------------
__global__ void scatter_kernel(const int* __restrict__ src, const int* __restrict__ dst) {
    int e = blockIdx.x * blockDim.x + threadIdx.x;
    if (e < NE) {
        int dn = dst[e];
        int p = d_offsets[dn] + d_rank[e];
        d_se[p] = make_int2(src[e], e);
    }
}

// ---------------- K4a: per-node sum of incident edge features (16-dim) ----------------
__global__ __launch_bounds__(256) void agg_edge_kernel(const float* __restrict__ ef) {
    int node = blockIdx.x * 8 + (threadIdx.x >> 5);
    if (node >= NN) return;
    int lane = threadIdx.x & 31;
    int s = d_offsets[node], e = d_offsets[node + 1];
    int f = lane & 15, half = lane >> 4;
    float acc0 = 0.f, acc1 = 0.f;
    int p = s + half;
    for (; p + 2 < e; p += 4) {
        int e0 = d_se[p].y;
        int e1 = d_se[p + 2].y;
        acc0 += ef[e0 * FE + f];
        acc1 += ef[e1 * FE + f];
    }
    if (p < e) acc0 += ef[d_se[p].y * FE + f];
    float acc = acc0 + acc1;
    acc += __shfl_xor_sync(0xffffffffu, acc, 16);
    if (lane < 16) d_agg16[node * FE + lane] = acc;
}

// ---------------- K4b: init via HMMA: msg = [nf|agg16] @ [Wn;We] + bn + deg*be ; h0 = relu ----------------
__global__ __launch_bounds__(128) void init_mma_kernel(
    const float* __restrict__ nf, const float* __restrict__ bn, const float* __restrict__ be) {
    __shared__ __half sX[64 * 88];   // 64 rows x 80 cols (stride 88)
    __shared__ __half sW[80 * 88];
    int t = threadIdx.x;
    int blockRow = blockIdx.x * 64;
    // X cols 0-63 from nf (fp32 -> fp16), guarded (nf is exactly NN rows)
    for (int idx = t; idx < 64 * 32; idx += 128) {
        int row = idx >> 5, c2 = idx & 31;
        int grow = blockRow + row;
        float2 v = (grow < NN) ? *(const float2*)(nf + grow * 64 + c2 * 2) : make_float2(0.f, 0.f);
        *(__half2*)(sX + row * 88 + c2 * 2) = __floats2half2_rn(v.x, v.y);
    }
    // X cols 64-79 from agg16
    for (int idx = t; idx < 64 * 8; idx += 128) {
        int row = idx >> 3, c2 = idx & 7;
        int grow = blockRow + row;
        float2 v = (grow < NN) ? *(const float2*)(d_agg16 + grow * 16 + c2 * 2) : make_float2(0.f, 0.f);
        *(__half2*)(sX + row * 88 + 64 + c2 * 2) = __floats2half2_rn(v.x, v.y);
    }
    // W: 80 x 64 fp16
    for (int idx = t; idx < 80 * 8; idx += 128) {
        int row = idx >> 3, ch = idx & 7;
        int4 v = *(const int4*)(d_Wni + row * 64 + ch * 8);
        *(int4*)(sW + row * 88 + ch * 8) = v;
    }
    __syncthreads();
    int w = t >> 5, lane = t & 31;
    uint32_t a[5][4];
#pragma unroll
    for (int kk = 0; kk < 5; kk++) {
        uint32_t addr = smem_u32(sX + (w * 16 + (lane & 15)) * 88 + kk * 16 + (lane >> 4) * 8);
        asm volatile("ldmatrix.sync.aligned.m8n8.x4.shared.b16 {%0,%1,%2,%3}, [%4];"
            : "=r"(a[kk][0]), "=r"(a[kk][1]), "=r"(a[kk][2]), "=r"(a[kk][3]) : "r"(addr));
    }
    __half2* msg2 = (__half2*)d_msg;
    __half2* h2 = (__half2*)d_hA;
#pragma unroll
    for (int n = 0; n < 8; n++) {
        float c0 = 0.f, c1 = 0.f, c2 = 0.f, c3 = 0.f;
#pragma unroll
        for (int kk = 0; kk < 5; kk++) {
            uint32_t b0, b1;
            uint32_t addr = smem_u32(sW + (kk * 16 + (lane & 15)) * 88 + n * 8);
            asm volatile("ldmatrix.sync.aligned.m8n8.x2.trans.shared.b16 {%0,%1}, [%2];"
                : "=r"(b0), "=r"(b1) : "r"(addr));
            asm volatile("mma.sync.aligned.m16n8k16.row.col.f32.f16.f16.f32 "
                "{%0,%1,%2,%3}, {%4,%5,%6,%7}, {%8,%9}, {%0,%1,%2,%3};"
                : "+f"(c0), "+f"(c1), "+f"(c2), "+f"(c3)
                : "r"(a[kk][0]), "r"(a[kk][1]), "r"(a[kk][2]), "r"(a[kk][3]), "r"(b0), "r"(b1));
        }
        int r0 = blockRow + w * 16 + (lane >> 2);
        int r1 = r0 + 8;
        int col = n * 8 + (lane & 3) * 2;
        float2 bnv = *(const float2*)(bn + col);
        float2 bev = *(const float2*)(be + col);
        float deg0 = (r0 < NN) ? (float)(d_offsets[r0 + 1] - d_offsets[r0]) : 0.f;
        float deg1 = (r1 < NN) ? (float)(d_offsets[r1 + 1] - d_offsets[r1]) : 0.f;
        float m00 = c0 + bnv.x + deg0 * bev.x;
        float m01 = c1 + bnv.y + deg0 * bev.y;
        float m10 = c2 + bnv.x + deg1 * bev.x;
        float m11 = c3 + bnv.y + deg1 * bev.y;
        msg2[r0 * 32 + (col >> 1)] = __floats2half2_rn(m00, m01);
        msg2[r1 * 32 + (col >> 1)] = __floats2half2_rn(m10, m11);
        h2[r0 * 32 + (col >> 1)] = __floats2half2_rn(fmaxf(m00, 0.f), fmaxf(m01, 0.f));
        h2[r1 * 32 + (col >> 1)] = __floats2half2_rn(fmaxf(m10, 0.f), fmaxf(m11, 0.f));
    }
}

// ---------------- K5: g = h @ Wc[lv] via HMMA (fp16 in/out, fp32 accum) ----------------
__global__ __launch_bounds__(128) void gemm_kernel(const __half* __restrict__ W16, int lv) {
    __shared__ __half sX[64 * 72];
    __shared__ __half sW[64 * 72];
    const __half* __restrict__ hin = (lv & 1) ? d_hB : d_hA;
    int t = threadIdx.x;
    int blockRow = blockIdx.x * 64;
    for (int idx = t; idx < 512; idx += 128) {
        int row = idx >> 3, ch = idx & 7;
        int4 v = *(const int4*)(hin + (blockRow + row) * 64 + ch * 8);
        *(int4*)(sX + row * 72 + ch * 8) = v;
    }
    for (int idx = t; idx < 512; idx += 128) {
        int row = idx >> 3, ch = idx & 7;
        int4 v = *(const int4*)(W16 + row * 64 + ch * 8);
        *(int4*)(sW + row * 72 + ch * 8) = v;
    }
    __syncthreads();
    int w = t >> 5, lane = t & 31;
    uint32_t a[4][4];
#pragma unroll
    for (int kk = 0; kk < 4; kk++) {
        uint32_t addr = smem_u32(sX + (w * 16 + (lane & 15)) * 72 + kk * 16 + (lane >> 4) * 8);
        asm volatile("ldmatrix.sync.aligned.m8n8.x4.shared.b16 {%0,%1,%2,%3}, [%4];"
            : "=r"(a[kk][0]), "=r"(a[kk][1]), "=r"(a[kk][2]), "=r"(a[kk][3]) : "r"(addr));
    }
    __half2* gout = (__half2*)d_g;
#pragma unroll
    for (int n = 0; n < 8; n++) {
        float c0 = 0.f, c1 = 0.f, c2 = 0.f, c3 = 0.f;
#pragma unroll
        for (int kk = 0; kk < 4; kk++) {
            uint32_t b0, b1;
            uint32_t addr = smem_u32(sW + (kk * 16 + (lane & 15)) * 72 + n * 8);
            asm volatile("ldmatrix.sync.aligned.m8n8.x2.trans.shared.b16 {%0,%1}, [%2];"
                : "=r"(b0), "=r"(b1) : "r"(addr));
            asm volatile("mma.sync.aligned.m16n8k16.row.col.f32.f16.f16.f32 "
                "{%0,%1,%2,%3}, {%4,%5,%6,%7}, {%8,%9}, {%0,%1,%2,%3};"
                : "+f"(c0), "+f"(c1), "+f"(c2), "+f"(c3)
                : "r"(a[kk][0]), "r"(a[kk][1]), "r"(a[kk][2]), "r"(a[kk][3]), "r"(b0), "r"(b1));
        }
        int r0 = blockRow + w * 16 + (lane >> 2);
        int col = n * 8 + (lane & 3) * 2;
        gout[r0 * 32 + (col >> 1)] = __floats2half2_rn(c0, c1);
        gout[(r0 + 8) * 32 + (col >> 1)] = __floats2half2_rn(c2, c3);
    }
}

// ---------------- K6: h' = relu( segsum_dst(g[src]) + b + msg )  (pure gather) ----------------
__global__ __launch_bounds__(512) void gather_kernel(const float* __restrict__ bc, int lv) {
    int warp = threadIdx.x >> 5, lane = threadIdx.x & 31;
    int node = blockIdx.x * 16 + warp;
    if (node >= NN) return;
    __half2* __restrict__ hout = (lv & 1) ? (__half2*)d_hA : (__half2*)d_hB;
    const __half2* __restrict__ g = (const __half2*)d_g;
    int s = d_offsets[node], e = d_offsets[node + 1];
    float2 acc0 = make_float2(0.f, 0.f), acc1 = make_float2(0.f, 0.f);
    float2 acc2 = make_float2(0.f, 0.f), acc3 = make_float2(0.f, 0.f);
    int p = s;
    for (; p + 4 <= e; p += 4) {
        int i0 = d_se[p].x, i1 = d_se[p + 1].x, i2 = d_se[p + 2].x, i3 = d_se[p + 3].x;
        float2 f0 = __half22float2(g[i0 * 32 + lane]);
        float2 f1 = __half22float2(g[i1 * 32 + lane]);
        float2 f2 = __half22float2(g[i2 * 32 + lane]);
        float2 f3 = __half22float2(g[i3 * 32 + lane]);
        acc0.x += f0.x; acc0.y += f0.y;
        acc1.x += f1.x; acc1.y += f1.y;
        acc2.x += f2.x; acc2.y += f2.y;
        acc3.x += f3.x; acc3.y += f3.y;
    }
    for (; p < e; p++) {
        float2 f = __half22float2(g[d_se[p].x * 32 + lane]);
        acc0.x += f.x; acc0.y += f.y;
    }
    float x0 = (acc0.x + acc1.x) + (acc2.x + acc3.x);
    float x1 = (acc0.y + acc1.y) + (acc2.y + acc3.y);
    float2 b2 = *(const float2*)(bc + 2 * lane);
    float2 mf = __half22float2(((const __half2*)d_msg)[node * 32 + lane]);
    float o0 = fmaxf(x0 + b2.x + mf.x, 0.f);
    float o1 = fmaxf(x1 + b2.y + mf.y, 0.f);
    hout[node * 32 + lane] = __floats2half2_rn(o0, o1);
}

// ---------------- K7: out = relu(h@Wf + bf) -> graph sum-pool ----------------
__global__ __launch_bounds__(256) void final_kernel(
    const float* __restrict__ Wf, const float* __restrict__ bf,
    const int* __restrict__ gid, float* __restrict__ out) {
    __shared__ float sW[64 * 64];
    __shared__ float sb[64];
    const __half2* __restrict__ X = (const __half2*)d_hB;  // 3 levels -> ends in B
    int t = threadIdx.x;
    for (int i = t; i < 4096; i += 256) sW[i] = Wf[i];
    if (t < 64) sb[t] = bf[t];
    __syncthreads();
    int warp = t >> 5, lane = t & 31;
    int rowbase = (blockIdx.x * 8 + warp) * 8;
    if (rowbase >= NN) return;
    const float2* sW2 = (const float2*)sW;
    float2 bb = ((const float2*)sb)[lane];
    float xa0[8], xa1[8], a0[8], a1[8];
#pragma unroll
    for (int r = 0; r < 8; r++) {
        int row = rowbase + r;
        bool v = row < NN;
        float2 f = v ? __half22float2(X[row * 32 + lane]) : make_float2(0.f, 0.f);
        xa0[r] = f.x;
        xa1[r] = f.y;
        a0[r] = bb.x;
        a1[r] = bb.y;
    }
#pragma unroll 2
    for (int kk = 0; kk < 32; kk++) {
        float2 wA = sW2[(2 * kk) * 32 + lane];
        float2 wB = sW2[(2 * kk + 1) * 32 + lane];
#pragma unroll
        for (int r = 0; r < 8; r++) {
            float xk0 = __shfl_sync(0xffffffffu, xa0[r], kk);
            float xk1 = __shfl_sync(0xffffffffu, xa1[r], kk);
            a0[r] += xk0 * wA.x + xk1 * wB.x;
            a1[r] += xk0 * wA.y + xk1 * wB.y;
        }
    }
#pragma unroll
    for (int r = 0; r < 8; r++) {
        a0[r] = fmaxf(a0[r], 0.f);
        a1[r] = fmaxf(a1[r], 0.f);
    }
    bool full = (rowbase + 8 <= NN);
    int g0 = gid[rowbase];
    bool uni = full;
    if (full) {
#pragma unroll
        for (int r = 1; r < 8; r++) uni = uni && (gid[rowbase + r] == g0);
    }
    if (uni) {
        float s0 = 0.f, s1 = 0.f;
#pragma unroll
        for (int r = 0; r < 8; r++) { s0 += a0[r]; s1 += a1[r]; }
        atomicAdd(&out[g0 * 64 + 2 * lane], s0);
        atomicAdd(&out[g0 * 64 + 2 * lane + 1], s1);
    } else {
#pragma unroll
        for (int r = 0; r < 8; r++) {
            int row = rowbase + r;
            if (row >= NN) break;
            int gg = gid[row];
            atomicAdd(&out[gg * 64 + 2 * lane], a0[r]);
            atomicAdd(&out[gg * 64 + 2 * lane + 1], a1[r]);
        }
    }
}

// ---------------- host ----------------
extern "C" void kernel_launch(void* const* d_in, const int* in_sizes, int n_in,
                              void* d_out, int out_size) {
    const float *nf = 0, *ef = 0, *Wn = 0, *bn = 0, *We = 0, *be = 0;
    const float *Wc = 0, *bc = 0, *Wf = 0, *bf = 0;
    const int *esrc = 0, *edst = 0, *gid = 0;
    int n800 = 0, n4096 = 0, n64 = 0;
    for (int i = 0; i < n_in; i++) {
        int sz = in_sizes[i];
        const void* p = d_in[i];
        if (sz == NN * 64)      nf = (const float*)p;
        else if (sz == NE * 16) ef = (const float*)p;
        else if (sz == NE)      { if (n800++ == 0) esrc = (const int*)p; else edst = (const int*)p; }
        else if (sz == NN)      gid = (const int*)p;
        else if (sz == 4096)    { if (n4096++ == 0) Wn = (const float*)p; else Wf = (const float*)p; }
        else if (sz == 1024)    We = (const float*)p;
        else if (sz == 12288)   Wc = (const float*)p;
        else if (sz == 192)     bc = (const float*)p;
        else if (sz == 64)      { if (n64 == 0) bn = (const float*)p;
                                  else if (n64 == 1) be = (const float*)p;
                                  else bf = (const float*)p; n64++; }
    }
    float* out = (float*)d_out;

    __half* Wc16_ptr;
    cudaGetSymbolAddress((void**)&Wc16_ptr, d_Wc16);

    zero_kernel<<<NBLK, 256>>>(out, Wn, We, Wc);
    hist_kernel<<<(NE + 255) / 256, 256>>>(edst);
    scan_kernel<<<NBLK, 256>>>();
    scatter_kernel<<<(NE + 255) / 256, 256>>>(esrc, edst);
    agg_edge_kernel<<<(NN + 7) / 8, 256>>>(ef);
    init_mma_kernel<<<NNPAD / 64, 128>>>(nf, bn, be);
    for (int lv = 0; lv < 3; lv++) {
        gemm_kernel<<<NNPAD / 64, 128>>>(Wc16_ptr + lv * 4096, lv);
        gather_kernel<<<(NN + 15) / 16, 512>>>(bc + lv * 64, lv);
    }
    final_kernel<<<(NN + 63) / 64, 256>>>(Wf, bf, gid, out);
}

// round 6
// speedup vs baseline: 2.1129x; 1.1146x over previous
#include <cuda_runtime.h>
#include <cuda_fp16.h>
#include <cstdint>

#define NN 50000
#define NNPAD 50048           // 782 * 64
#define NE 800000
#define NG 128
#define FE 16
#define DD 64
#define NBLK ((NN + 255) / 256)   // 196 scan blocks

// ---------------- scratch (static device globals; no allocation) ----------------
__device__ int    d_counts[NN];
__device__ int    d_offsets[NN + 1];
__device__ int    d_rank[NE];
__device__ unsigned long long d_scanstate[NBLK];
__device__ int2   d_se[NE];          // (src, eid) packed, CSR order by dst
__device__ float  d_agg16[NNPAD * FE];
__device__ __half d_msg[NNPAD * DD];
__device__ __half d_hA[NNPAD * DD];
__device__ __half d_hB[NNPAD * DD];
__device__ __half d_g[NNPAD * DD];
__device__ __half d_Wni[80 * 64];    // rows 0-63: W_n2l, rows 64-79: W_e2l
__device__ __half d_Wc16[3 * 64 * 64];
__device__ __half d_Wf16[64 * 64];

__device__ __forceinline__ uint32_t smem_u32(const void* p) {
    return (uint32_t)__cvta_generic_to_shared(p);
}

// ---------------- K0: zero output/counters/scanstate + convert weights to fp16 ----------------
__global__ void zero_kernel(float* __restrict__ out, const float* __restrict__ Wn,
                            const float* __restrict__ We, const float* __restrict__ Wc,
                            const float* __restrict__ Wf) {
    int i = blockIdx.x * blockDim.x + threadIdx.x;
    if (i < NG * DD) out[i] = 0.f;
    if (i < NN) d_counts[i] = 0;
    if (i < NBLK) d_scanstate[i] = 0ULL;
    if (i == 0) d_offsets[NN] = NE;
    if (i < 4096) { d_Wni[i] = __float2half(Wn[i]); d_Wf16[i] = __float2half(Wf[i]); }
    else if (i < 5120) d_Wni[i] = __float2half(We[i - 4096]);
    if (i < 12288) d_Wc16[i] = __float2half(Wc[i]);
}

// ---------------- K1: histogram of edge_dst; atomic return = rank within bucket ----------------
__global__ void hist_kernel(const int* __restrict__ dst) {
    int e = blockIdx.x * blockDim.x + threadIdx.x;
    if (e < NE) d_rank[e] = atomicAdd(&d_counts[dst[e]], 1);
}

// ---------------- K2: single-pass decoupled-lookback exclusive scan -> offsets ----------------
__global__ __launch_bounds__(256) void scan_kernel() {
    __shared__ int sm[256];
    __shared__ int s_excl;
    int b = blockIdx.x, t = threadIdx.x;
    int i = b * 256 + t;
    int v = (i < NN) ? d_counts[i] : 0;
    sm[t] = v;
    __syncthreads();
#pragma unroll
    for (int d = 1; d < 256; d <<= 1) {
        int x = (t >= d) ? sm[t - d] : 0;
        __syncthreads();
        sm[t] += x;
        __syncthreads();
    }
    int incl = sm[t];
    int agg = sm[255];
    if (t == 0) {
        unsigned long long fl = (b == 0) ? 2ULL : 1ULL;
        atomicExch(&d_scanstate[b], (fl << 32) | (unsigned long long)(unsigned)agg);
        if (b == 0) s_excl = 0;
    }
    if (b > 0 && t < 32) {
        int lane = t;
        int j = b - 1;
        int excl = 0;
        while (true) {
            int idx = j - lane;
            unsigned long long s;
            if (idx >= 0) {
                do { s = atomicAdd(&d_scanstate[idx], 0ULL); } while ((s >> 32) == 0ULL);
            } else {
                s = (2ULL << 32);
            }
            unsigned fl = (unsigned)(s >> 32);
            int val = (int)(unsigned)(s & 0xffffffffULL);
            unsigned mask = __ballot_sync(0xffffffffu, fl == 2u);
            if (mask) {
                int lmin = __ffs(mask) - 1;
                int contrib = (lane <= lmin) ? val : 0;
#pragma unroll
                for (int o = 16; o > 0; o >>= 1) contrib += __shfl_down_sync(0xffffffffu, contrib, o);
                contrib = __shfl_sync(0xffffffffu, contrib, 0);
                excl += contrib;
                break;
            } else {
                int contrib = val;
#pragma unroll
                for (int o = 16; o > 0; o >>= 1) contrib += __shfl_down_sync(0xffffffffu, contrib, o);
                contrib = __shfl_sync(0xffffffffu, contrib, 0);
                excl += contrib;
                j -= 32;
            }
        }
        if (lane == 0) {
            atomicExch(&d_scanstate[b], (2ULL << 32) | (unsigned long long)(unsigned)(excl + agg));
            s_excl = excl;
        }
    }
    __syncthreads();
    if (i < NN) d_offsets[i] = s_excl + incl - v;
}

// ---------------- K3: scatter edges into CSR order (atomic-free) ----------------
__global__ void scatter_kernel(const int* __restrict__ src, const int* __restrict__ dst) {
    int e = blockIdx.x * blockDim.x + threadIdx.x;
    if (e < NE) {
        int dn = dst[e];
        int p = d_offsets[dn] + d_rank[e];
        d_se[p] = make_int2(src[e], e);
    }
}

// ---------------- K4a: per-node sum of incident edge features (16-dim) ----------------
__global__ __launch_bounds__(256) void agg_edge_kernel(const float* __restrict__ ef) {
    int node = blockIdx.x * 8 + (threadIdx.x >> 5);
    if (node >= NN) return;
    int lane = threadIdx.x & 31;
    int s = d_offsets[node], e = d_offsets[node + 1];
    int f = lane & 15, half = lane >> 4;
    float acc0 = 0.f, acc1 = 0.f;
    int p = s + half;
    for (; p + 2 < e; p += 4) {
        int e0 = d_se[p].y;
        int e1 = d_se[p + 2].y;
        acc0 += ef[e0 * FE + f];
        acc1 += ef[e1 * FE + f];
    }
    if (p < e) acc0 += ef[d_se[p].y * FE + f];
    float acc = acc0 + acc1;
    acc += __shfl_xor_sync(0xffffffffu, acc, 16);
    if (lane < 16) d_agg16[node * FE + lane] = acc;
}

// ---------------- K4b: init via HMMA: msg = [nf|agg16] @ [Wn;We] + bn + deg*be ; h0 = relu ----------------
__global__ __launch_bounds__(128) void init_mma_kernel(
    const float* __restrict__ nf, const float* __restrict__ bn, const float* __restrict__ be) {
    __shared__ __half sX[64 * 88];   // 64 rows x 80 cols (stride 88)
    __shared__ __half sW[80 * 88];
    int t = threadIdx.x;
    int blockRow = blockIdx.x * 64;
    for (int idx = t; idx < 64 * 32; idx += 128) {
        int row = idx >> 5, c2 = idx & 31;
        int grow = blockRow + row;
        float2 v = (grow < NN) ? *(const float2*)(nf + grow * 64 + c2 * 2) : make_float2(0.f, 0.f);
        *(__half2*)(sX + row * 88 + c2 * 2) = __floats2half2_rn(v.x, v.y);
    }
    for (int idx = t; idx < 64 * 8; idx += 128) {
        int row = idx >> 3, c2 = idx & 7;
        int grow = blockRow + row;
        float2 v = (grow < NN) ? *(const float2*)(d_agg16 + grow * 16 + c2 * 2) : make_float2(0.f, 0.f);
        *(__half2*)(sX + row * 88 + 64 + c2 * 2) = __floats2half2_rn(v.x, v.y);
    }
    for (int idx = t; idx < 80 * 8; idx += 128) {
        int row = idx >> 3, ch = idx & 7;
        int4 v = *(const int4*)(d_Wni + row * 64 + ch * 8);
        *(int4*)(sW + row * 88 + ch * 8) = v;
    }
    __syncthreads();
    int w = t >> 5, lane = t & 31;
    uint32_t a[5][4];
#pragma unroll
    for (int kk = 0; kk < 5; kk++) {
        uint32_t addr = smem_u32(sX + (w * 16 + (lane & 15)) * 88 + kk * 16 + (lane >> 4) * 8);
        asm volatile("ldmatrix.sync.aligned.m8n8.x4.shared.b16 {%0,%1,%2,%3}, [%4];"
            : "=r"(a[kk][0]), "=r"(a[kk][1]), "=r"(a[kk][2]), "=r"(a[kk][3]) : "r"(addr));
    }
    __half2* msg2 = (__half2*)d_msg;
    __half2* h2 = (__half2*)d_hA;
#pragma unroll
    for (int n = 0; n < 8; n++) {
        float c0 = 0.f, c1 = 0.f, c2 = 0.f, c3 = 0.f;
#pragma unroll
        for (int kk = 0; kk < 5; kk++) {
            uint32_t b0, b1;
            uint32_t addr = smem_u32(sW + (kk * 16 + (lane & 15)) * 88 + n * 8);
            asm volatile("ldmatrix.sync.aligned.m8n8.x2.trans.shared.b16 {%0,%1}, [%2];"
                : "=r"(b0), "=r"(b1) : "r"(addr));
            asm volatile("mma.sync.aligned.m16n8k16.row.col.f32.f16.f16.f32 "
                "{%0,%1,%2,%3}, {%4,%5,%6,%7}, {%8,%9}, {%0,%1,%2,%3};"
                : "+f"(c0), "+f"(c1), "+f"(c2), "+f"(c3)
                : "r"(a[kk][0]), "r"(a[kk][1]), "r"(a[kk][2]), "r"(a[kk][3]), "r"(b0), "r"(b1));
        }
        int r0 = blockRow + w * 16 + (lane >> 2);
        int r1 = r0 + 8;
        int col = n * 8 + (lane & 3) * 2;
        float2 bnv = *(const float2*)(bn + col);
        float2 bev = *(const float2*)(be + col);
        float deg0 = (r0 < NN) ? (float)(d_offsets[r0 + 1] - d_offsets[r0]) : 0.f;
        float deg1 = (r1 < NN) ? (float)(d_offsets[r1 + 1] - d_offsets[r1]) : 0.f;
        float m00 = c0 + bnv.x + deg0 * bev.x;
        float m01 = c1 + bnv.y + deg0 * bev.y;
        float m10 = c2 + bnv.x + deg1 * bev.x;
        float m11 = c3 + bnv.y + deg1 * bev.y;
        msg2[r0 * 32 + (col >> 1)] = __floats2half2_rn(m00, m01);
        msg2[r1 * 32 + (col >> 1)] = __floats2half2_rn(m10, m11);
        h2[r0 * 32 + (col >> 1)] = __floats2half2_rn(fmaxf(m00, 0.f), fmaxf(m01, 0.f));
        h2[r1 * 32 + (col >> 1)] = __floats2half2_rn(fmaxf(m10, 0.f), fmaxf(m11, 0.f));
    }
}

// ---------------- K5: g = h @ Wc[lv] via HMMA (fp16 in/out, fp32 accum) ----------------
__global__ __launch_bounds__(128) void gemm_kernel(const __half* __restrict__ W16, int lv) {
    __shared__ __half sX[64 * 72];
    __shared__ __half sW[64 * 72];
    const __half* __restrict__ hin = (lv & 1) ? d_hB : d_hA;
    int t = threadIdx.x;
    int blockRow = blockIdx.x * 64;
    for (int idx = t; idx < 512; idx += 128) {
        int row = idx >> 3, ch = idx & 7;
        int4 v = *(const int4*)(hin + (blockRow + row) * 64 + ch * 8);
        *(int4*)(sX + row * 72 + ch * 8) = v;
    }
    for (int idx = t; idx < 512; idx += 128) {
        int row = idx >> 3, ch = idx & 7;
        int4 v = *(const int4*)(W16 + row * 64 + ch * 8);
        *(int4*)(sW + row * 72 + ch * 8) = v;
    }
    __syncthreads();
    int w = t >> 5, lane = t & 31;
    uint32_t a[4][4];
#pragma unroll
    for (int kk = 0; kk < 4; kk++) {
        uint32_t addr = smem_u32(sX + (w * 16 + (lane & 15)) * 72 + kk * 16 + (lane >> 4) * 8);
        asm volatile("ldmatrix.sync.aligned.m8n8.x4.shared.b16 {%0,%1,%2,%3}, [%4];"
            : "=r"(a[kk][0]), "=r"(a[kk][1]), "=r"(a[kk][2]), "=r"(a[kk][3]) : "r"(addr));
    }
    __half2* gout = (__half2*)d_g;
#pragma unroll
    for (int n = 0; n < 8; n++) {
        float c0 = 0.f, c1 = 0.f, c2 = 0.f, c3 = 0.f;
#pragma unroll
        for (int kk = 0; kk < 4; kk++) {
            uint32_t b0, b1;
            uint32_t addr = smem_u32(sW + (kk * 16 + (lane & 15)) * 72 + n * 8);
            asm volatile("ldmatrix.sync.aligned.m8n8.x2.trans.shared.b16 {%0,%1}, [%2];"
                : "=r"(b0), "=r"(b1) : "r"(addr));
            asm volatile("mma.sync.aligned.m16n8k16.row.col.f32.f16.f16.f32 "
                "{%0,%1,%2,%3}, {%4,%5,%6,%7}, {%8,%9}, {%0,%1,%2,%3};"
                : "+f"(c0), "+f"(c1), "+f"(c2), "+f"(c3)
                : "r"(a[kk][0]), "r"(a[kk][1]), "r"(a[kk][2]), "r"(a[kk][3]), "r"(b0), "r"(b1));
        }
        int r0 = blockRow + w * 16 + (lane >> 2);
        int col = n * 8 + (lane & 3) * 2;
        gout[r0 * 32 + (col >> 1)] = __floats2half2_rn(c0, c1);
        gout[(r0 + 8) * 32 + (col >> 1)] = __floats2half2_rn(c2, c3);
    }
}

// ---------------- K6: h' = relu( segsum_dst(g[src]) + b + msg )  (pure gather) ----------------
__global__ __launch_bounds__(512) void gather_kernel(const float* __restrict__ bc, int lv) {
    int warp = threadIdx.x >> 5, lane = threadIdx.x & 31;
    int node = blockIdx.x * 16 + warp;
    if (node >= NN) return;
    __half2* __restrict__ hout = (lv & 1) ? (__half2*)d_hA : (__half2*)d_hB;
    const __half2* __restrict__ g = (const __half2*)d_g;
    int s = d_offsets[node], e = d_offsets[node + 1];
    float2 acc0 = make_float2(0.f, 0.f), acc1 = make_float2(0.f, 0.f);
    float2 acc2 = make_float2(0.f, 0.f), acc3 = make_float2(0.f, 0.f);
    int p = s;
    for (; p + 4 <= e; p += 4) {
        int i0 = d_se[p].x, i1 = d_se[p + 1].x, i2 = d_se[p + 2].x, i3 = d_se[p + 3].x;
        float2 f0 = __half22float2(g[i0 * 32 + lane]);
        float2 f1 = __half22float2(g[i1 * 32 + lane]);
        float2 f2 = __half22float2(g[i2 * 32 + lane]);
        float2 f3 = __half22float2(g[i3 * 32 + lane]);
        acc0.x += f0.x; acc0.y += f0.y;
        acc1.x += f1.x; acc1.y += f1.y;
        acc2.x += f2.x; acc2.y += f2.y;
        acc3.x += f3.x; acc3.y += f3.y;
    }
    for (; p < e; p++) {
        float2 f = __half22float2(g[d_se[p].x * 32 + lane]);
        acc0.x += f.x; acc0.y += f.y;
    }
    float x0 = (acc0.x + acc1.x) + (acc2.x + acc3.x);
    float x1 = (acc0.y + acc1.y) + (acc2.y + acc3.y);
    float2 b2 = *(const float2*)(bc + 2 * lane);
    float2 mf = __half22float2(((const __half2*)d_msg)[node * 32 + lane]);
    float o0 = fmaxf(x0 + b2.x + mf.x, 0.f);
    float o1 = fmaxf(x1 + b2.y + mf.y, 0.f);
    hout[node * 32 + lane] = __floats2half2_rn(o0, o1);
}

// ---------------- K7: HMMA final: relu(h@Wf + bf) -> graph sum-pool ----------------
__global__ __launch_bounds__(128) void final_mma_kernel(
    const float* __restrict__ bf, const int* __restrict__ gid, float* __restrict__ out) {
    __shared__ __half sX[64 * 72];
    __shared__ __half sW[64 * 72];
    __shared__ float sOut[64 * 65];
    const __half* __restrict__ hin = d_hB;   // 3 levels -> h3 in B
    int t = threadIdx.x;
    int blockRow = blockIdx.x * 64;
    for (int idx = t; idx < 512; idx += 128) {
        int row = idx >> 3, ch = idx & 7;
        int4 v = *(const int4*)(hin + (blockRow + row) * 64 + ch * 8);
        *(int4*)(sX + row * 72 + ch * 8) = v;
    }
    for (int idx = t; idx < 512; idx += 128) {
        int row = idx >> 3, ch = idx & 7;
        int4 v = *(const int4*)(d_Wf16 + row * 64 + ch * 8);
        *(int4*)(sW + row * 72 + ch * 8) = v;
    }
    __syncthreads();
    int w = t >> 5, lane = t & 31;
    uint32_t a[4][4];
#pragma unroll
    for (int kk = 0; kk < 4; kk++) {
        uint32_t addr = smem_u32(sX + (w * 16 + (lane & 15)) * 72 + kk * 16 + (lane >> 4) * 8);
        asm volatile("ldmatrix.sync.aligned.m8n8.x4.shared.b16 {%0,%1,%2,%3}, [%4];"
            : "=r"(a[kk][0]), "=r"(a[kk][1]), "=r"(a[kk][2]), "=r"(a[kk][3]) : "r"(addr));
    }
#pragma unroll
    for (int n = 0; n < 8; n++) {
        float c0 = 0.f, c1 = 0.f, c2 = 0.f, c3 = 0.f;
#pragma unroll
        for (int kk = 0; kk < 4; kk++) {
            uint32_t b0, b1;
            uint32_t addr = smem_u32(sW + (kk * 16 + (lane & 15)) * 72 + n * 8);
            asm volatile("ldmatrix.sync.aligned.m8n8.x2.trans.shared.b16 {%0,%1}, [%2];"
                : "=r"(b0), "=r"(b1) : "r"(addr));
            asm volatile("mma.sync.aligned.m16n8k16.row.col.f32.f16.f16.f32 "
                "{%0,%1,%2,%3}, {%4,%5,%6,%7}, {%8,%9}, {%0,%1,%2,%3};"
                : "+f"(c0), "+f"(c1), "+f"(c2), "+f"(c3)
                : "r"(a[kk][0]), "r"(a[kk][1]), "r"(a[kk][2]), "r"(a[kk][3]), "r"(b0), "r"(b1));
        }
        int rl0 = w * 16 + (lane >> 2);
        int col = n * 8 + (lane & 3) * 2;
        float2 bv = *(const float2*)(bf + col);
        sOut[rl0 * 65 + col]           = fmaxf(c0 + bv.x, 0.f);
        sOut[rl0 * 65 + col + 1]       = fmaxf(c1 + bv.y, 0.f);
        sOut[(rl0 + 8) * 65 + col]     = fmaxf(c2 + bv.x, 0.f);
        sOut[(rl0 + 8) * 65 + col + 1] = fmaxf(c3 + bv.y, 0.f);
    }
    __syncthreads();
    // pooling: warp w handles local rows [w*16, w*16+16)
    int gr = blockRow + w * 16;
    int nvalid = NN - gr;
    if (nvalid <= 0) return;
    bool uni = false;
    int g0 = 0;
    if (nvalid >= 16) {
        int gv = gid[gr + (lane & 15)];
        g0 = __shfl_sync(0xffffffffu, gv, 0);
        uni = __all_sync(0xffffffffu, gv == g0);
    }
    if (uni) {
        float s0 = 0.f, s1 = 0.f;
#pragma unroll
        for (int r = 0; r < 16; r++) {
            s0 += sOut[(w * 16 + r) * 65 + lane];
            s1 += sOut[(w * 16 + r) * 65 + lane + 32];
        }
        atomicAdd(&out[g0 * 64 + lane], s0);
        atomicAdd(&out[g0 * 64 + lane + 32], s1);
    } else {
        for (int r = 0; r < 16; r++) {
            int row = gr + r;
            if (row >= NN) break;
            int gg = gid[row];
            atomicAdd(&out[gg * 64 + lane], sOut[(w * 16 + r) * 65 + lane]);
            atomicAdd(&out[gg * 64 + lane + 32], sOut[(w * 16 + r) * 65 + lane + 32]);
        }
    }
}

// ---------------- host ----------------
extern "C" void kernel_launch(void* const* d_in, const int* in_sizes, int n_in,
                              void* d_out, int out_size) {
    const float *nf = 0, *ef = 0, *Wn = 0, *bn = 0, *We = 0, *be = 0;
    const float *Wc = 0, *bc = 0, *Wf = 0, *bf = 0;
    const int *esrc = 0, *edst = 0, *gid = 0;
    int n800 = 0, n4096 = 0, n64 = 0;
    for (int i = 0; i < n_in; i++) {
        int sz = in_sizes[i];
        const void* p = d_in[i];
        if (sz == NN * 64)      nf = (const float*)p;
        else if (sz == NE * 16) ef = (const float*)p;
        else if (sz == NE)      { if (n800++ == 0) esrc = (const int*)p; else edst = (const int*)p; }
        else if (sz == NN)      gid = (const int*)p;
        else if (sz == 4096)    { if (n4096++ == 0) Wn = (const float*)p; else Wf = (const float*)p; }
        else if (sz == 1024)    We = (const float*)p;
        else if (sz == 12288)   Wc = (const float*)p;
        else if (sz == 192)     bc = (const float*)p;
        else if (sz == 64)      { if (n64 == 0) bn = (const float*)p;
                                  else if (n64 == 1) be = (const float*)p;
                                  else bf = (const float*)p; n64++; }
    }
    float* out = (float*)d_out;

    __half* Wc16_ptr;
    cudaGetSymbolAddress((void**)&Wc16_ptr, d_Wc16);

    zero_kernel<<<NBLK, 256>>>(out, Wn, We, Wc, Wf);
    hist_kernel<<<(NE + 255) / 256, 256>>>(edst);
    scan_kernel<<<NBLK, 256>>>();
    scatter_kernel<<<(NE + 255) / 256, 256>>>(esrc, edst);
    agg_edge_kernel<<<(NN + 7) / 8, 256>>>(ef);
    init_mma_kernel<<<NNPAD / 64, 128>>>(nf, bn, be);
    for (int lv = 0; lv < 3; lv++) {
        gemm_kernel<<<NNPAD / 64, 128>>>(Wc16_ptr + lv * 4096, lv);
        gather_kernel<<<(NN + 15) / 16, 512>>>(bc + lv * 64, lv);
    }
    final_mma_kernel<<<NNPAD / 64, 128>>>(bf, gid, out);
}

// round 7
// speedup vs baseline: 2.1952x; 1.0390x over previous
#include <cuda_runtime.h>
#include <cuda_fp16.h>
#include <cstdint>

#define NN 50000
#define NNPAD 50048           // 782 * 64
#define NE 800000
#define NG 128
#define FE 16
#define DD 64
#define NBLK ((NN + 255) / 256)   // 196 scan blocks

// ---------------- scratch (static device globals; no allocation) ----------------
__device__ int    d_counts[NN];          // starts 0; re-zeroed by scan_kernel each run
__device__ int    d_offsets[NN + 1];
__device__ int    d_rank[NE];
__device__ unsigned long long d_scanstate[NBLK];  // starts 0; re-zeroed by scatter_kernel
__device__ int2   d_se[NE];              // (src, eid) packed, CSR order by dst
__device__ float  d_agg16[NNPAD * FE];
__device__ __half d_msg[NNPAD * DD];
__device__ __half d_hA[NNPAD * DD];
__device__ __half d_hB[NNPAD * DD];
__device__ __half d_Wni[80 * 64];        // rows 0-63: W_n2l, rows 64-79: W_e2l
__device__ __half d_Wc16[3 * 64 * 64];
__device__ __half d_Wf16[64 * 64];

__device__ __forceinline__ uint32_t smem_u32(const void* p) {
    return (uint32_t)__cvta_generic_to_shared(p);
}

// ---------------- K1: histogram of edge_dst (rank trick) + fp16 weight conversion ----------------
__global__ void hist_kernel(const int* __restrict__ dst,
                            const float* __restrict__ Wn, const float* __restrict__ We,
                            const float* __restrict__ Wc, const float* __restrict__ Wf) {
    int e = blockIdx.x * blockDim.x + threadIdx.x;
    if (e < NE) d_rank[e] = atomicAdd(&d_counts[dst[e]], 1);
    if (e < 4096) { d_Wni[e] = __float2half(Wn[e]); d_Wf16[e] = __float2half(Wf[e]); }
    else if (e < 5120) d_Wni[e] = __float2half(We[e - 4096]);
    if (e < 12288) d_Wc16[e] = __float2half(Wc[e]);
}

// ---------------- K2: single-pass decoupled-lookback exclusive scan -> offsets; re-zero counts ----------------
__global__ __launch_bounds__(256) void scan_kernel() {
    __shared__ int sm[256];
    __shared__ int s_excl;
    int b = blockIdx.x, t = threadIdx.x;
    int i = b * 256 + t;
    int v = (i < NN) ? d_counts[i] : 0;
    sm[t] = v;
    __syncthreads();
#pragma unroll
    for (int d = 1; d < 256; d <<= 1) {
        int x = (t >= d) ? sm[t - d] : 0;
        __syncthreads();
        sm[t] += x;
        __syncthreads();
    }
    int incl = sm[t];
    int agg = sm[255];
    if (t == 0) {
        unsigned long long fl = (b == 0) ? 2ULL : 1ULL;
        atomicExch(&d_scanstate[b], (fl << 32) | (unsigned long long)(unsigned)agg);
        if (b == 0) s_excl = 0;
    }
    if (b > 0 && t < 32) {
        int lane = t;
        int j = b - 1;
        int excl = 0;
        while (true) {
            int idx = j - lane;
            unsigned long long s;
            if (idx >= 0) {
                do { s = atomicAdd(&d_scanstate[idx], 0ULL); } while ((s >> 32) == 0ULL);
            } else {
                s = (2ULL << 32);
            }
            unsigned fl = (unsigned)(s >> 32);
            int val = (int)(unsigned)(s & 0xffffffffULL);
            unsigned mask = __ballot_sync(0xffffffffu, fl == 2u);
            if (mask) {
                int lmin = __ffs(mask) - 1;
                int contrib = (lane <= lmin) ? val : 0;
#pragma unroll
                for (int o = 16; o > 0; o >>= 1) contrib += __shfl_down_sync(0xffffffffu, contrib, o);
                contrib = __shfl_sync(0xffffffffu, contrib, 0);
                excl += contrib;
                break;
            } else {
                int contrib = val;
#pragma unroll
                for (int o = 16; o > 0; o >>= 1) contrib += __shfl_down_sync(0xffffffffu, contrib, o);
                contrib = __shfl_sync(0xffffffffu, contrib, 0);
                excl += contrib;
                j -= 32;
            }
        }
        if (lane == 0) {
            atomicExch(&d_scanstate[b], (2ULL << 32) | (unsigned long long)(unsigned)(excl + agg));
            s_excl = excl;
        }
    }
    __syncthreads();
    if (i < NN) {
        d_offsets[i] = s_excl + incl - v;
        d_counts[i] = 0;          // restore invariant for next graph replay
    }
    if (b == NBLK - 1 && t == 0) d_offsets[NN] = NE;
}

// ---------------- K3: scatter edges into CSR order (atomic-free); re-zero scanstate ----------------
__global__ void scatter_kernel(const int* __restrict__ src, const int* __restrict__ dst) {
    int e = blockIdx.x * blockDim.x + threadIdx.x;
    if (e < NE) {
        int dn = dst[e];
        int p = d_offsets[dn] + d_rank[e];
        d_se[p] = make_int2(src[e], e);
    }
    if (e < NBLK) d_scanstate[e] = 0ULL;   // restore invariant
}

// ---------------- K4a: per-node sum of incident edge features (16-dim) ----------------
__global__ __launch_bounds__(256) void agg_edge_kernel(const float* __restrict__ ef) {
    int node = blockIdx.x * 8 + (threadIdx.x >> 5);
    if (node >= NN) return;
    int lane = threadIdx.x & 31;
    int s = d_offsets[node], e = d_offsets[node + 1];
    int f = lane & 15, half = lane >> 4;
    float acc0 = 0.f, acc1 = 0.f;
    int p = s + half;
    for (; p + 2 < e; p += 4) {
        int e0 = d_se[p].y;
        int e1 = d_se[p + 2].y;
        acc0 += ef[e0 * FE + f];
        acc1 += ef[e1 * FE + f];
    }
    if (p < e) acc0 += ef[d_se[p].y * FE + f];
    float acc = acc0 + acc1;
    acc += __shfl_xor_sync(0xffffffffu, acc, 16);
    if (lane < 16) d_agg16[node * FE + lane] = acc;
}

// ---------------- K4b: init via HMMA: msg = [nf|agg16] @ [Wn;We] + bn + deg*be ; h0 = relu ----------------
__global__ __launch_bounds__(128) void init_mma_kernel(
    const float* __restrict__ nf, const float* __restrict__ bn, const float* __restrict__ be) {
    __shared__ __half sX[64 * 88];   // 64 rows x 80 cols (stride 88)
    __shared__ __half sW[80 * 88];
    int t = threadIdx.x;
    int blockRow = blockIdx.x * 64;
    for (int idx = t; idx < 64 * 32; idx += 128) {
        int row = idx >> 5, c2 = idx & 31;
        int grow = blockRow + row;
        float2 v = (grow < NN) ? *(const float2*)(nf + grow * 64 + c2 * 2) : make_float2(0.f, 0.f);
        *(__half2*)(sX + row * 88 + c2 * 2) = __floats2half2_rn(v.x, v.y);
    }
    for (int idx = t; idx < 64 * 8; idx += 128) {
        int row = idx >> 3, c2 = idx & 7;
        int grow = blockRow + row;
        float2 v = (grow < NN) ? *(const float2*)(d_agg16 + grow * 16 + c2 * 2) : make_float2(0.f, 0.f);
        *(__half2*)(sX + row * 88 + 64 + c2 * 2) = __floats2half2_rn(v.x, v.y);
    }
    for (int idx = t; idx < 80 * 8; idx += 128) {
        int row = idx >> 3, ch = idx & 7;
        int4 v = *(const int4*)(d_Wni + row * 64 + ch * 8);
        *(int4*)(sW + row * 88 + ch * 8) = v;
    }
    __syncthreads();
    int w = t >> 5, lane = t & 31;
    uint32_t a[5][4];
#pragma unroll
    for (int kk = 0; kk < 5; kk++) {
        uint32_t addr = smem_u32(sX + (w * 16 + (lane & 15)) * 88 + kk * 16 + (lane >> 4) * 8);
        asm volatile("ldmatrix.sync.aligned.m8n8.x4.shared.b16 {%0,%1,%2,%3}, [%4];"
            : "=r"(a[kk][0]), "=r"(a[kk][1]), "=r"(a[kk][2]), "=r"(a[kk][3]) : "r"(addr));
    }
    __half2* msg2 = (__half2*)d_msg;
    __half2* h2 = (__half2*)d_hA;
#pragma unroll
    for (int n = 0; n < 8; n++) {
        float c0 = 0.f, c1 = 0.f, c2 = 0.f, c3 = 0.f;
#pragma unroll
        for (int kk = 0; kk < 5; kk++) {
            uint32_t b0, b1;
            uint32_t addr = smem_u32(sW + (kk * 16 + (lane & 15)) * 88 + n * 8);
            asm volatile("ldmatrix.sync.aligned.m8n8.x2.trans.shared.b16 {%0,%1}, [%2];"
                : "=r"(b0), "=r"(b1) : "r"(addr));
            asm volatile("mma.sync.aligned.m16n8k16.row.col.f32.f16.f16.f32 "
                "{%0,%1,%2,%3}, {%4,%5,%6,%7}, {%8,%9}, {%0,%1,%2,%3};"
                : "+f"(c0), "+f"(c1), "+f"(c2), "+f"(c3)
                : "r"(a[kk][0]), "r"(a[kk][1]), "r"(a[kk][2]), "r"(a[kk][3]), "r"(b0), "r"(b1));
        }
        int r0 = blockRow + w * 16 + (lane >> 2);
        int r1 = r0 + 8;
        int col = n * 8 + (lane & 3) * 2;
        float2 bnv = *(const float2*)(bn + col);
        float2 bev = *(const float2*)(be + col);
        float deg0 = (r0 < NN) ? (float)(d_offsets[r0 + 1] - d_offsets[r0]) : 0.f;
        float deg1 = (r1 < NN) ? (float)(d_offsets[r1 + 1] - d_offsets[r1]) : 0.f;
        float m00 = c0 + bnv.x + deg0 * bev.x;
        float m01 = c1 + bnv.y + deg0 * bev.y;
        float m10 = c2 + bnv.x + deg1 * bev.x;
        float m11 = c3 + bnv.y + deg1 * bev.y;
        msg2[r0 * 32 + (col >> 1)] = __floats2half2_rn(m00, m01);
        msg2[r1 * 32 + (col >> 1)] = __floats2half2_rn(m10, m11);
        h2[r0 * 32 + (col >> 1)] = __floats2half2_rn(fmaxf(m00, 0.f), fmaxf(m01, 0.f));
        h2[r1 * 32 + (col >> 1)] = __floats2half2_rn(fmaxf(m10, 0.f), fmaxf(m11, 0.f));
    }
}

// ---------------- K6: fused gather+GEMM: h' = relu( pool(h)[16 nodes] @ W + b + msg ) ----------------
// 512 threads = 16 warps = 16 nodes per block. 50000 = 3125 * 16 exactly.
__global__ __launch_bounds__(512) void gather_mma_kernel(
    const __half* __restrict__ W16, const float* __restrict__ bc, int lv,
    float* __restrict__ out) {
    __shared__ __half sW[64 * 72];
    __shared__ __half sPool[16 * 72];
    int t = threadIdx.x;
    int warp = t >> 5, lane = t & 31;
    // zero the output accumulator during the last level (runs right before final_mma)
    if (lv == 2) {
        int gtid = blockIdx.x * 512 + t;
        if (gtid < NG * DD) out[gtid] = 0.f;
    }
    // stage W
    for (int idx = t; idx < 512; idx += 512) {
        int row = idx >> 3, ch = idx & 7;
        int4 v = *(const int4*)(W16 + row * 64 + ch * 8);
        *(int4*)(sW + row * 72 + ch * 8) = v;
    }
    const __half2* __restrict__ hin = (lv & 1) ? (const __half2*)d_hB : (const __half2*)d_hA;
    __half2* __restrict__ hout = (lv & 1) ? (__half2*)d_hA : (__half2*)d_hB;

    int node = blockIdx.x * 16 + warp;
    int s = d_offsets[node], e = d_offsets[node + 1];
    float2 acc0 = make_float2(0.f, 0.f), acc1 = make_float2(0.f, 0.f);
    float2 acc2 = make_float2(0.f, 0.f), acc3 = make_float2(0.f, 0.f);
    int p = s;
    for (; p + 4 <= e; p += 4) {
        int i0 = d_se[p].x, i1 = d_se[p + 1].x, i2 = d_se[p + 2].x, i3 = d_se[p + 3].x;
        float2 f0 = __half22float2(hin[i0 * 32 + lane]);
        float2 f1 = __half22float2(hin[i1 * 32 + lane]);
        float2 f2 = __half22float2(hin[i2 * 32 + lane]);
        float2 f3 = __half22float2(hin[i3 * 32 + lane]);
        acc0.x += f0.x; acc0.y += f0.y;
        acc1.x += f1.x; acc1.y += f1.y;
        acc2.x += f2.x; acc2.y += f2.y;
        acc3.x += f3.x; acc3.y += f3.y;
    }
    for (; p < e; p++) {
        float2 f = __half22float2(hin[d_se[p].x * 32 + lane]);
        acc0.x += f.x; acc0.y += f.y;
    }
    float x0 = (acc0.x + acc1.x) + (acc2.x + acc3.x);
    float x1 = (acc0.y + acc1.y) + (acc2.y + acc3.y);
    *(__half2*)(sPool + warp * 72 + 2 * lane) = __floats2half2_rn(x0, x1);
    __syncthreads();

    // warps 0-7: each computes all 16 rows x 8-col stripe [warp*8, warp*8+8)
    if (warp < 8) {
        float c0 = 0.f, c1 = 0.f, c2 = 0.f, c3 = 0.f;
#pragma unroll
        for (int kk = 0; kk < 4; kk++) {
            uint32_t a0, a1, a2, a3;
            uint32_t addrA = smem_u32(sPool + (lane & 15) * 72 + kk * 16 + (lane >> 4) * 8);
            asm volatile("ldmatrix.sync.aligned.m8n8.x4.shared.b16 {%0,%1,%2,%3}, [%4];"
                : "=r"(a0), "=r"(a1), "=r"(a2), "=r"(a3) : "r"(addrA));
            uint32_t b0, b1;
            uint32_t addrB = smem_u32(sW + (kk * 16 + (lane & 15)) * 72 + warp * 8);
            asm volatile("ldmatrix.sync.aligned.m8n8.x2.trans.shared.b16 {%0,%1}, [%2];"
                : "=r"(b0), "=r"(b1) : "r"(addrB));
            asm volatile("mma.sync.aligned.m16n8k16.row.col.f32.f16.f16.f32 "
                "{%0,%1,%2,%3}, {%4,%5,%6,%7}, {%8,%9}, {%0,%1,%2,%3};"
                : "+f"(c0), "+f"(c1), "+f"(c2), "+f"(c3)
                : "r"(a0), "r"(a1), "r"(a2), "r"(a3), "r"(b0), "r"(b1));
        }
        int r0 = lane >> 2;           // local rows 0..7 ; r1 = r0+8
        int col = warp * 8 + (lane & 3) * 2;
        int n0 = blockIdx.x * 16 + r0;
        int n1 = n0 + 8;
        float2 bv = *(const float2*)(bc + col);
        float2 m0 = __half22float2(((const __half2*)d_msg)[n0 * 32 + (col >> 1)]);
        float2 m1 = __half22float2(((const __half2*)d_msg)[n1 * 32 + (col >> 1)]);
        float o00 = fmaxf(c0 + bv.x + m0.x, 0.f);
        float o01 = fmaxf(c1 + bv.y + m0.y, 0.f);
        float o10 = fmaxf(c2 + bv.x + m1.x, 0.f);
        float o11 = fmaxf(c3 + bv.y + m1.y, 0.f);
        hout[n0 * 32 + (col >> 1)] = __floats2half2_rn(o00, o01);
        hout[n1 * 32 + (col >> 1)] = __floats2half2_rn(o10, o11);
    }
}

// ---------------- K7: HMMA final: relu(h@Wf + bf) -> graph sum-pool ----------------
__global__ __launch_bounds__(128) void final_mma_kernel(
    const float* __restrict__ bf, const int* __restrict__ gid, float* __restrict__ out) {
    __shared__ __half sX[64 * 72];
    __shared__ __half sW[64 * 72];
    __shared__ float sOut[64 * 65];
    const __half* __restrict__ hin = d_hB;   // 3 levels -> h3 in B
    int t = threadIdx.x;
    int blockRow = blockIdx.x * 64;
    for (int idx = t; idx < 512; idx += 128) {
        int row = idx >> 3, ch = idx & 7;
        int4 v = *(const int4*)(hin + (blockRow + row) * 64 + ch * 8);
        *(int4*)(sX + row * 72 + ch * 8) = v;
    }
    for (int idx = t; idx < 512; idx += 128) {
        int row = idx >> 3, ch = idx & 7;
        int4 v = *(const int4*)(d_Wf16 + row * 64 + ch * 8);
        *(int4*)(sW + row * 72 + ch * 8) = v;
    }
    __syncthreads();
    int w = t >> 5, lane = t & 31;
    uint32_t a[4][4];
#pragma unroll
    for (int kk = 0; kk < 4; kk++) {
        uint32_t addr = smem_u32(sX + (w * 16 + (lane & 15)) * 72 + kk * 16 + (lane >> 4) * 8);
        asm volatile("ldmatrix.sync.aligned.m8n8.x4.shared.b16 {%0,%1,%2,%3}, [%4];"
            : "=r"(a[kk][0]), "=r"(a[kk][1]), "=r"(a[kk][2]), "=r"(a[kk][3]) : "r"(addr));
    }
#pragma unroll
    for (int n = 0; n < 8; n++) {
        float c0 = 0.f, c1 = 0.f, c2 = 0.f, c3 = 0.f;
#pragma unroll
        for (int kk = 0; kk < 4; kk++) {
            uint32_t b0, b1;
            uint32_t addr = smem_u32(sW + (kk * 16 + (lane & 15)) * 72 + n * 8);
            asm volatile("ldmatrix.sync.aligned.m8n8.x2.trans.shared.b16 {%0,%1}, [%2];"
                : "=r"(b0), "=r"(b1) : "r"(addr));
            asm volatile("mma.sync.aligned.m16n8k16.row.col.f32.f16.f16.f32 "
                "{%0,%1,%2,%3}, {%4,%5,%6,%7}, {%8,%9}, {%0,%1,%2,%3};"
                : "+f"(c0), "+f"(c1), "+f"(c2), "+f"(c3)
                : "r"(a[kk][0]), "r"(a[kk][1]), "r"(a[kk][2]), "r"(a[kk][3]), "r"(b0), "r"(b1));
        }
        int rl0 = w * 16 + (lane >> 2);
        int col = n * 8 + (lane & 3) * 2;
        float2 bv = *(const float2*)(bf + col);
        sOut[rl0 * 65 + col]           = fmaxf(c0 + bv.x, 0.f);
        sOut[rl0 * 65 + col + 1]       = fmaxf(c1 + bv.y, 0.f);
        sOut[(rl0 + 8) * 65 + col]     = fmaxf(c2 + bv.x, 0.f);
        sOut[(rl0 + 8) * 65 + col + 1] = fmaxf(c3 + bv.y, 0.f);
    }
    __syncthreads();
    int gr = blockRow + w * 16;
    int nvalid = NN - gr;
    if (nvalid <= 0) return;
    bool uni = false;
    int g0 = 0;
    if (nvalid >= 16) {
        int gv = gid[gr + (lane & 15)];
        g0 = __shfl_sync(0xffffffffu, gv, 0);
        uni = __all_sync(0xffffffffu, gv == g0);
    }
    if (uni) {
        float s0 = 0.f, s1 = 0.f;
#pragma unroll
        for (int r = 0; r < 16; r++) {
            s0 += sOut[(w * 16 + r) * 65 + lane];
            s1 += sOut[(w * 16 + r) * 65 + lane + 32];
        }
        atomicAdd(&out[g0 * 64 + lane], s0);
        atomicAdd(&out[g0 * 64 + lane + 32], s1);
    } else {
        for (int r = 0; r < 16; r++) {
            int row = gr + r;
            if (row >= NN) break;
            int gg = gid[row];
            atomicAdd(&out[gg * 64 + lane], sOut[(w * 16 + r) * 65 + lane]);
            atomicAdd(&out[gg * 64 + lane + 32], sOut[(w * 16 + r) * 65 + lane + 32]);
        }
    }
}

// ---------------- host ----------------
extern "C" void kernel_launch(void* const* d_in, const int* in_sizes, int n_in,
                              void* d_out, int out_size) {
    const float *nf = 0, *ef = 0, *Wn = 0, *bn = 0, *We = 0, *be = 0;
    const float *Wc = 0, *bc = 0, *Wf = 0, *bf = 0;
    const int *esrc = 0, *edst = 0, *gid = 0;
    int n800 = 0, n4096 = 0, n64 = 0;
    for (int i = 0; i < n_in; i++) {
        int sz = in_sizes[i];
        const void* p = d_in[i];
        if (sz == NN * 64)      nf = (const float*)p;
        else if (sz == NE * 16) ef = (const float*)p;
        else if (sz == NE)      { if (n800++ == 0) esrc = (const int*)p; else edst = (const int*)p; }
        else if (sz == NN)      gid = (const int*)p;
        else if (sz == 4096)    { if (n4096++ == 0) Wn = (const float*)p; else Wf = (const float*)p; }
        else if (sz == 1024)    We = (const float*)p;
        else if (sz == 12288)   Wc = (const float*)p;
        else if (sz == 192)     bc = (const float*)p;
        else if (sz == 64)      { if (n64 == 0) bn = (const float*)p;
                                  else if (n64 == 1) be = (const float*)p;
                                  else bf = (const float*)p; n64++; }
    }
    float* out = (float*)d_out;

    __half* Wc16_ptr;
    cudaGetSymbolAddress((void**)&Wc16_ptr, d_Wc16);

    hist_kernel<<<(NE + 255) / 256, 256>>>(edst, Wn, We, Wc, Wf);
    scan_kernel<<<NBLK, 256>>>();
    scatter_kernel<<<(NE + 255) / 256, 256>>>(esrc, edst);
    agg_edge_kernel<<<(NN + 7) / 8, 256>>>(ef);
    init_mma_kernel<<<NNPAD / 64, 128>>>(nf, bn, be);
    for (int lv = 0; lv < 3; lv++)
        gather_mma_kernel<<<NN / 16, 512>>>(Wc16_ptr + lv * 4096, bc + lv * 64, lv, out);
    final_mma_kernel<<<NNPAD / 64, 128>>>(bf, gid, out);
}

// round 9
// speedup vs baseline: 2.2259x; 1.0140x over previous
#include <cuda_runtime.h>
#include <cuda_fp16.h>
#include <cstdint>

#define NN 50000
#define NNPAD 50048           // 782 * 64
#define NE 800000
#define NG 128
#define FE 16
#define DD 64
#define NBLK ((NN + 255) / 256)   // 196 scan blocks

// ---------------- scratch (static device globals; no allocation) ----------------
__device__ int    d_counts[NN];          // starts 0; re-zeroed by scan_kernel each run
__device__ int    d_offsets[NN + 1];
__device__ int    d_rank[NE];
__device__ unsigned long long d_scanstate[NBLK];  // starts 0; re-zeroed by scatter_kernel
__device__ int    d_src[NE];             // src node per CSR slot (sorted by dst)
__device__ __half d_ef16p[NE * FE];      // edge features permuted into CSR order, fp16
__device__ float  d_agg16[NNPAD * FE];
__device__ __half d_msg[NNPAD * DD];
__device__ __half d_hA[NNPAD * DD];
__device__ __half d_hB[NNPAD * DD];
__device__ __half d_Wni[80 * 64];        // rows 0-63: W_n2l, rows 64-79: W_e2l
__device__ __half d_Wc16[3 * 64 * 64];
__device__ __half d_Wf16[64 * 64];

__device__ __forceinline__ uint32_t smem_u32(const void* p) {
    return (uint32_t)__cvta_generic_to_shared(p);
}

__device__ __forceinline__ uint32_t h2u(__half2 h) {
    return *reinterpret_cast<uint32_t*>(&h);
}

// ---------------- K1: histogram of edge_dst (rank trick) + fp16 weight conversion ----------------
__global__ void hist_kernel(const int* __restrict__ dst,
                            const float* __restrict__ Wn, const float* __restrict__ We,
                            const float* __restrict__ Wc, const float* __restrict__ Wf) {
    int e = blockIdx.x * blockDim.x + threadIdx.x;
    if (e < NE) d_rank[e] = atomicAdd(&d_counts[dst[e]], 1);
    if (e < 4096) { d_Wni[e] = __float2half(Wn[e]); d_Wf16[e] = __float2half(Wf[e]); }
    else if (e < 5120) d_Wni[e] = __float2half(We[e - 4096]);
    if (e < 12288) d_Wc16[e] = __float2half(Wc[e]);
}

// ---------------- K2: single-pass decoupled-lookback exclusive scan -> offsets; re-zero counts ----------------
__global__ __launch_bounds__(256) void scan_kernel() {
    __shared__ int sm[256];
    __shared__ int s_excl;
    int b = blockIdx.x, t = threadIdx.x;
    int i = b * 256 + t;
    int v = (i < NN) ? d_counts[i] : 0;
    sm[t] = v;
    __syncthreads();
#pragma unroll
    for (int d = 1; d < 256; d <<= 1) {
        int x = (t >= d) ? sm[t - d] : 0;
        __syncthreads();
        sm[t] += x;
        __syncthreads();
    }
    int incl = sm[t];
    int agg = sm[255];
    if (t == 0) {
        unsigned long long fl = (b == 0) ? 2ULL : 1ULL;
        atomicExch(&d_scanstate[b], (fl << 32) | (unsigned long long)(unsigned)agg);
        if (b == 0) s_excl = 0;
    }
    if (b > 0 && t < 32) {
        int lane = t;
        int j = b - 1;
        int excl = 0;
        while (true) {
            int idx = j - lane;
            unsigned long long s;
            if (idx >= 0) {
                do { s = atomicAdd(&d_scanstate[idx], 0ULL); } while ((s >> 32) == 0ULL);
            } else {
                s = (2ULL << 32);
            }
            unsigned fl = (unsigned)(s >> 32);
            int val = (int)(unsigned)(s & 0xffffffffULL);
            unsigned mask = __ballot_sync(0xffffffffu, fl == 2u);
            if (mask) {
                int lmin = __ffs(mask) - 1;
                int contrib = (lane <= lmin) ? val : 0;
#pragma unroll
                for (int o = 16; o > 0; o >>= 1) contrib += __shfl_down_sync(0xffffffffu, contrib, o);
                contrib = __shfl_sync(0xffffffffu, contrib, 0);
                excl += contrib;
                break;
            } else {
                int contrib = val;
#pragma unroll
                for (int o = 16; o > 0; o >>= 1) contrib += __shfl_down_sync(0xffffffffu, contrib, o);
                contrib = __shfl_sync(0xffffffffu, contrib, 0);
                excl += contrib;
                j -= 32;
            }
        }
        if (lane == 0) {
            atomicExch(&d_scanstate[b], (2ULL << 32) | (unsigned long long)(unsigned)(excl + agg));
            s_excl = excl;
        }
    }
    __syncthreads();
    if (i < NN) {
        d_offsets[i] = s_excl + incl - v;
        d_counts[i] = 0;          // restore invariant for next graph replay
    }
    if (b == NBLK - 1 && t == 0) d_offsets[NN] = NE;
}

// ---------------- K3: scatter edges into CSR order + permute edge features to fp16 ----------------
__global__ void scatter_kernel(const int* __restrict__ src, const int* __restrict__ dst,
                               const float* __restrict__ ef) {
    int e = blockIdx.x * blockDim.x + threadIdx.x;
    if (e < NE) {
        int dn = dst[e];
        int p = d_offsets[dn] + d_rank[e];
        d_src[p] = src[e];
        // coalesced 64B read of edge features, convert, 2x16B scattered writes
        const float4* efr = (const float4*)(ef + e * FE);
        float4 v0 = efr[0], v1 = efr[1], v2 = efr[2], v3 = efr[3];
        uint4 q0 = make_uint4(h2u(__floats2half2_rn(v0.x, v0.y)),
                              h2u(__floats2half2_rn(v0.z, v0.w)),
                              h2u(__floats2half2_rn(v1.x, v1.y)),
                              h2u(__floats2half2_rn(v1.z, v1.w)));
        uint4 q1 = make_uint4(h2u(__floats2half2_rn(v2.x, v2.y)),
                              h2u(__floats2half2_rn(v2.z, v2.w)),
                              h2u(__floats2half2_rn(v3.x, v3.y)),
                              h2u(__floats2half2_rn(v3.z, v3.w)));
        *(uint4*)(d_ef16p + p * FE) = q0;
        *(uint4*)(d_ef16p + p * FE + 8) = q1;
    }
    if (e < NBLK) d_scanstate[e] = 0ULL;   // restore invariant
}

// ---------------- K4a: per-node sum of incident edge features (coalesced CSR walk) ----------------
// warp per node; 8 lanes per edge (half2 granularity), 4 edges in flight per warp.
__global__ __launch_bounds__(256) void agg_edge_kernel() {
    int node = blockIdx.x * 8 + (threadIdx.x >> 5);
    if (node >= NN) return;
    int lane = threadIdx.x & 31;
    int f2 = lane & 7;        // half2 index within row (0..7)
    int eg = lane >> 3;       // edge subgroup (0..3)
    int s = d_offsets[node], e = d_offsets[node + 1];
    const __half2* __restrict__ pf = (const __half2*)d_ef16p;
    float2 acc = make_float2(0.f, 0.f);
    for (int base = s; base < e; base += 4) {
        int p = base + eg;
        if (p < e) {
            float2 fv = __half22float2(pf[p * 8 + f2]);
            acc.x += fv.x;
            acc.y += fv.y;
        }
    }
    // reduce across the 4 edge subgroups (lanes differing in bits 3,4)
    acc.x += __shfl_xor_sync(0xffffffffu, acc.x, 8);
    acc.y += __shfl_xor_sync(0xffffffffu, acc.y, 8);
    acc.x += __shfl_xor_sync(0xffffffffu, acc.x, 16);
    acc.y += __shfl_xor_sync(0xffffffffu, acc.y, 16);
    if (lane < 8) *(float2*)(d_agg16 + node * FE + f2 * 2) = acc;
}

// ---------------- K4b: init via HMMA: msg = [nf|agg16] @ [Wn;We] + bn + deg*be ; h0 = relu ----------------
__global__ __launch_bounds__(128) void init_mma_kernel(
    const float* __restrict__ nf, const float* __restrict__ bn, const float* __restrict__ be) {
    __shared__ __half sX[64 * 88];   // 64 rows x 80 cols (stride 88)
    __shared__ __half sW[80 * 88];
    int t = threadIdx.x;
    int blockRow = blockIdx.x * 64;
    for (int idx = t; idx < 64 * 32; idx += 128) {
        int row = idx >> 5, c2 = idx & 31;
        int grow = blockRow + row;
        float2 v = (grow < NN) ? *(const float2*)(nf + grow * 64 + c2 * 2) : make_float2(0.f, 0.f);
        *(__half2*)(sX + row * 88 + c2 * 2) = __floats2half2_rn(v.x, v.y);
    }
    for (int idx = t; idx < 64 * 8; idx += 128) {
        int row = idx >> 3, c2 = idx & 7;
        int grow = blockRow + row;
        float2 v = (grow < NN) ? *(const float2*)(d_agg16 + grow * 16 + c2 * 2) : make_float2(0.f, 0.f);
        *(__half2*)(sX + row * 88 + 64 + c2 * 2) = __floats2half2_rn(v.x, v.y);
    }
    for (int idx = t; idx < 80 * 8; idx += 128) {
        int row = idx >> 3, ch = idx & 7;
        int4 v = *(const int4*)(d_Wni + row * 64 + ch * 8);
        *(int4*)(sW + row * 88 + ch * 8) = v;
    }
    __syncthreads();
    int w = t >> 5, lane = t & 31;
    uint32_t a[5][4];
#pragma unroll
    for (int kk = 0; kk < 5; kk++) {
        uint32_t addr = smem_u32(sX + (w * 16 + (lane & 15)) * 88 + kk * 16 + (lane >> 4) * 8);
        asm volatile("ldmatrix.sync.aligned.m8n8.x4.shared.b16 {%0,%1,%2,%3}, [%4];"
            : "=r"(a[kk][0]), "=r"(a[kk][1]), "=r"(a[kk][2]), "=r"(a[kk][3]) : "r"(addr));
    }
    __half2* msg2 = (__half2*)d_msg;
    __half2* h2 = (__half2*)d_hA;
#pragma unroll
    for (int n = 0; n < 8; n++) {
        float c0 = 0.f, c1 = 0.f, c2 = 0.f, c3 = 0.f;
#pragma unroll
        for (int kk = 0; kk < 5; kk++) {
            uint32_t b0, b1;
            uint32_t addr = smem_u32(sW + (kk * 16 + (lane & 15)) * 88 + n * 8);
            asm volatile("ldmatrix.sync.aligned.m8n8.x2.trans.shared.b16 {%0,%1}, [%2];"
                : "=r"(b0), "=r"(b1) : "r"(addr));
            asm volatile("mma.sync.aligned.m16n8k16.row.col.f32.f16.f16.f32 "
                "{%0,%1,%2,%3}, {%4,%5,%6,%7}, {%8,%9}, {%0,%1,%2,%3};"
                : "+f"(c0), "+f"(c1), "+f"(c2), "+f"(c3)
                : "r"(a[kk][0]), "r"(a[kk][1]), "r"(a[kk][2]), "r"(a[kk][3]), "r"(b0), "r"(b1));
        }
        int r0 = blockRow + w * 16 + (lane >> 2);
        int r1 = r0 + 8;
        int col = n * 8 + (lane & 3) * 2;
        float2 bnv = *(const float2*)(bn + col);
        float2 bev = *(const float2*)(be + col);
        float deg0 = (r0 < NN) ? (float)(d_offsets[r0 + 1] - d_offsets[r0]) : 0.f;
        float deg1 = (r1 < NN) ? (float)(d_offsets[r1 + 1] - d_offsets[r1]) : 0.f;
        float m00 = c0 + bnv.x + deg0 * bev.x;
        float m01 = c1 + bnv.y + deg0 * bev.y;
        float m10 = c2 + bnv.x + deg1 * bev.x;
        float m11 = c3 + bnv.y + deg1 * bev.y;
        msg2[r0 * 32 + (col >> 1)] = __floats2half2_rn(m00, m01);
        msg2[r1 * 32 + (col >> 1)] = __floats2half2_rn(m10, m11);
        h2[r0 * 32 + (col >> 1)] = __floats2half2_rn(fmaxf(m00, 0.f), fmaxf(m01, 0.f));
        h2[r1 * 32 + (col >> 1)] = __floats2half2_rn(fmaxf(m10, 0.f), fmaxf(m11, 0.f));
    }
}

// ---------------- K6: fused gather+GEMM: h' = relu( pool(h)[16 nodes] @ W + b + msg ) ----------------
__global__ __launch_bounds__(512) void gather_mma_kernel(
    const __half* __restrict__ W16, const float* __restrict__ bc, int lv,
    float* __restrict__ out) {
    __shared__ __half sW[64 * 72];
    __shared__ __half sPool[16 * 72];
    int t = threadIdx.x;
    int warp = t >> 5, lane = t & 31;
    if (lv == 2) {
        int gtid = blockIdx.x * 512 + t;
        if (gtid < NG * DD) out[gtid] = 0.f;
    }
    for (int idx = t; idx < 512; idx += 512) {
        int row = idx >> 3, ch = idx & 7;
        int4 v = *(const int4*)(W16 + row * 64 + ch * 8);
        *(int4*)(sW + row * 72 + ch * 8) = v;
    }
    const __half2* __restrict__ hin = (lv & 1) ? (const __half2*)d_hB : (const __half2*)d_hA;
    __half2* __restrict__ hout = (lv & 1) ? (__half2*)d_hA : (__half2*)d_hB;

    int node = blockIdx.x * 16 + warp;
    int s = d_offsets[node], e = d_offsets[node + 1];
    float2 acc0 = make_float2(0.f, 0.f), acc1 = make_float2(0.f, 0.f);
    float2 acc2 = make_float2(0.f, 0.f), acc3 = make_float2(0.f, 0.f);
    int p = s;
    for (; p + 4 <= e; p += 4) {
        int i0 = d_src[p], i1 = d_src[p + 1], i2 = d_src[p + 2], i3 = d_src[p + 3];
        float2 f0 = __half22float2(hin[i0 * 32 + lane]);
        float2 f1 = __half22float2(hin[i1 * 32 + lane]);
        float2 f2 = __half22float2(hin[i2 * 32 + lane]);
        float2 f3 = __half22float2(hin[i3 * 32 + lane]);
        acc0.x += f0.x; acc0.y += f0.y;
        acc1.x += f1.x; acc1.y += f1.y;
        acc2.x += f2.x; acc2.y += f2.y;
        acc3.x += f3.x; acc3.y += f3.y;
    }
    for (; p < e; p++) {
        float2 f = __half22float2(hin[d_src[p] * 32 + lane]);
        acc0.x += f.x; acc0.y += f.y;
    }
    float x0 = (acc0.x + acc1.x) + (acc2.x + acc3.x);
    float x1 = (acc0.y + acc1.y) + (acc2.y + acc3.y);
    *(__half2*)(sPool + warp * 72 + 2 * lane) = __floats2half2_rn(x0, x1);
    __syncthreads();

    if (warp < 8) {
        float c0 = 0.f, c1 = 0.f, c2 = 0.f, c3 = 0.f;
#pragma unroll
        for (int kk = 0; kk < 4; kk++) {
            uint32_t a0, a1, a2, a3;
            uint32_t addrA = smem_u32(sPool + (lane & 15) * 72 + kk * 16 + (lane >> 4) * 8);
            asm volatile("ldmatrix.sync.aligned.m8n8.x4.shared.b16 {%0,%1,%2,%3}, [%4];"
                : "=r"(a0), "=r"(a1), "=r"(a2), "=r"(a3) : "r"(addrA));
            uint32_t b0, b1;
            uint32_t addrB = smem_u32(sW + (kk * 16 + (lane & 15)) * 72 + warp * 8);
            asm volatile("ldmatrix.sync.aligned.m8n8.x2.trans.shared.b16 {%0,%1}, [%2];"
                : "=r"(b0), "=r"(b1) : "r"(addrB));
            asm volatile("mma.sync.aligned.m16n8k16.row.col.f32.f16.f16.f32 "
                "{%0,%1,%2,%3}, {%4,%5,%6,%7}, {%8,%9}, {%0,%1,%2,%3};"
                : "+f"(c0), "+f"(c1), "+f"(c2), "+f"(c3)
                : "r"(a0), "r"(a1), "r"(a2), "r"(a3), "r"(b0), "r"(b1));
        }
        int r0 = lane >> 2;
        int col = warp * 8 + (lane & 3) * 2;
        int n0 = blockIdx.x * 16 + r0;
        int n1 = n0 + 8;
        float2 bv = *(const float2*)(bc + col);
        float2 m0 = __half22float2(((const __half2*)d_msg)[n0 * 32 + (col >> 1)]);
        float2 m1 = __half22float2(((const __half2*)d_msg)[n1 * 32 + (col >> 1)]);
        float o00 = fmaxf(c0 + bv.x + m0.x, 0.f);
        float o01 = fmaxf(c1 + bv.y + m0.y, 0.f);
        float o10 = fmaxf(c2 + bv.x + m1.x, 0.f);
        float o11 = fmaxf(c3 + bv.y + m1.y, 0.f);
        hout[n0 * 32 + (col >> 1)] = __floats2half2_rn(o00, o01);
        hout[n1 * 32 + (col >> 1)] = __floats2half2_rn(o10, o11);
    }
}

// ---------------- K7: HMMA final: relu(h@Wf + bf) -> graph sum-pool ----------------
__global__ __launch_bounds__(128) void final_mma_kernel(
    const float* __restrict__ bf, const int* __restrict__ gid, float* __restrict__ out) {
    __shared__ __half sX[64 * 72];
    __shared__ __half sW[64 * 72];
    __shared__ float sOut[64 * 65];
    const __half* __restrict__ hin = d_hB;   // 3 levels -> h3 in B
    int t = threadIdx.x;
    int blockRow = blockIdx.x * 64;
    for (int idx = t; idx < 512; idx += 128) {
        int row = idx >> 3, ch = idx & 7;
        int4 v = *(const int4*)(hin + (blockRow + row) * 64 + ch * 8);
        *(int4*)(sX + row * 72 + ch * 8) = v;
    }
    for (int idx = t; idx < 512; idx += 128) {
        int row = idx >> 3, ch = idx & 7;
        int4 v = *(const int4*)(d_Wf16 + row * 64 + ch * 8);
        *(int4*)(sW + row * 72 + ch * 8) = v;
    }
    __syncthreads();
    int w = t >> 5, lane = t & 31;
    uint32_t a[4][4];
#pragma unroll
    for (int kk = 0; kk < 4; kk++) {
        uint32_t addr = smem_u32(sX + (w * 16 + (lane & 15)) * 72 + kk * 16 + (lane >> 4) * 8);
        asm volatile("ldmatrix.sync.aligned.m8n8.x4.shared.b16 {%0,%1,%2,%3}, [%4];"
            : "=r"(a[kk][0]), "=r"(a[kk][1]), "=r"(a[kk][2]), "=r"(a[kk][3]) : "r"(addr));
    }
#pragma unroll
    for (int n = 0; n < 8; n++) {
        float c0 = 0.f, c1 = 0.f, c2 = 0.f, c3 = 0.f;
#pragma unroll
        for (int kk = 0; kk < 4; kk++) {
            uint32_t b0, b1;
            uint32_t addr = smem_u32(sW + (kk * 16 + (lane & 15)) * 72 + n * 8);
            asm volatile("ldmatrix.sync.aligned.m8n8.x2.trans.shared.b16 {%0,%1}, [%2];"
                : "=r"(b0), "=r"(b1) : "r"(addr));
            asm volatile("mma.sync.aligned.m16n8k16.row.col.f32.f16.f16.f32 "
                "{%0,%1,%2,%3}, {%4,%5,%6,%7}, {%8,%9}, {%0,%1,%2,%3};"
                : "+f"(c0), "+f"(c1), "+f"(c2), "+f"(c3)
                : "r"(a[kk][0]), "r"(a[kk][1]), "r"(a[kk][2]), "r"(a[kk][3]), "r"(b0), "r"(b1));
        }
        int rl0 = w * 16 + (lane >> 2);
        int col = n * 8 + (lane & 3) * 2;
        float2 bv = *(const float2*)(bf + col);
        sOut[rl0 * 65 + col]           = fmaxf(c0 + bv.x, 0.f);
        sOut[rl0 * 65 + col + 1]       = fmaxf(c1 + bv.y, 0.f);
        sOut[(rl0 + 8) * 65 + col]     = fmaxf(c2 + bv.x, 0.f);
        sOut[(rl0 + 8) * 65 + col + 1] = fmaxf(c3 + bv.y, 0.f);
    }
    __syncthreads();
    int gr = blockRow + w * 16;
    int nvalid = NN - gr;
    if (nvalid <= 0) return;
    bool uni = false;
    int g0 = 0;
    if (nvalid >= 16) {
        int gv = gid[gr + (lane & 15)];
        g0 = __shfl_sync(0xffffffffu, gv, 0);
        uni = __all_sync(0xffffffffu, gv == g0);
    }
    if (uni) {
        float s0 = 0.f, s1 = 0.f;
#pragma unroll
        for (int r = 0; r < 16; r++) {
            s0 += sOut[(w * 16 + r) * 65 + lane];
            s1 += sOut[(w * 16 + r) * 65 + lane + 32];
        }
        atomicAdd(&out[g0 * 64 + lane], s0);
        atomicAdd(&out[g0 * 64 + lane + 32], s1);
    } else {
        for (int r = 0; r < 16; r++) {
            int row = gr + r;
            if (row >= NN) break;
            int gg = gid[row];
            atomicAdd(&out[gg * 64 + lane], sOut[(w * 16 + r) * 65 + lane]);
            atomicAdd(&out[gg * 64 + lane + 32], sOut[(w * 16 + r) * 65 + lane + 32]);
        }
    }
}

// ---------------- host ----------------
extern "C" void kernel_launch(void* const* d_in, const int* in_sizes, int n_in,
                              void* d_out, int out_size) {
    const float *nf = 0, *ef = 0, *Wn = 0, *bn = 0, *We = 0, *be = 0;
    const float *Wc = 0, *bc = 0, *Wf = 0, *bf = 0;
    const int *esrc = 0, *edst = 0, *gid = 0;
    int n800 = 0, n4096 = 0, n64 = 0;
    for (int i = 0; i < n_in; i++) {
        int sz = in_sizes[i];
        const void* p = d_in[i];
        if (sz == NN * 64)      nf = (const float*)p;
        else if (sz == NE * 16) ef = (const float*)p;
        else if (sz == NE)      { if (n800++ == 0) esrc = (const int*)p; else edst = (const int*)p; }
        else if (sz == NN)      gid = (const int*)p;
        else if (sz == 4096)    { if (n4096++ == 0) Wn = (const float*)p; else Wf = (const float*)p; }
        else if (sz == 1024)    We = (const float*)p;
        else if (sz == 12288)   Wc = (const float*)p;
        else if (sz == 192)     bc = (const float*)p;
        else if (sz == 64)      { if (n64 == 0) bn = (const float*)p;
                                  else if (n64 == 1) be = (const float*)p;
                                  else bf = (const float*)p; n64++; }
    }
    float* out = (float*)d_out;

    __half* Wc16_ptr;
    cudaGetSymbolAddress((void**)&Wc16_ptr, d_Wc16);

    hist_kernel<<<(NE + 255) / 256, 256>>>(edst, Wn, We, Wc, Wf);
    scan_kernel<<<NBLK, 256>>>();
    scatter_kernel<<<(NE + 255) / 256, 256>>>(esrc, edst, ef);
    agg_edge_kernel<<<(NN + 7) / 8, 256>>>();
    init_mma_kernel<<<NNPAD / 64, 128>>>(nf, bn, be);
    for (int lv = 0; lv < 3; lv++)
        gather_mma_kernel<<<NN / 16, 512>>>(Wc16_ptr + lv * 4096, bc + lv * 64, lv, out);
    final_mma_kernel<<<NNPAD / 64, 128>>>(bf, gid, out);
}